// round 7
// baseline (speedup 1.0000x reference)
#include <cuda_runtime.h>
#include <cuda_fp16.h>
#include <math.h>

// ---------------- problem constants ----------------
#define DIMC   384
#define NPIX   4096
#define BATCH  16
#define HEADS  4
#define CH     96
#define QKVROWS 1152
#define QSCALE 0.1020620726159658f   // 96^-0.5
#define CTX_SPLIT 8

// ---------------- scratch (device globals; allocation-free contract) ----------------
__device__ float  g_Wg[QKVROWS * DIMC];
__device__ float  g_wsum[QKVROWS];
__device__ float  g_mean[BATCH * NPIX];
__device__ float  g_rstd[BATCH * NPIX];
__device__ float  g_mean2[BATCH * NPIX];
__device__ float  g_rstd2[BATCH * NPIX];
__device__ __half g_qkvh[(size_t)BATCH * QKVROWS * NPIX];   // 151 MB, fp16
__device__ float  g_ctxT[BATCH * HEADS * CH * CH];          // ctx^T: [bh][e][d]
__device__ __half g_attnh[(size_t)BATCH * DIMC * NPIX];     // 50 MB, fp16
__device__ float  g_y[(size_t)BATCH * DIMC * NPIX];         // 100 MB

// ---------------- prep: W' = fp16-rounded(Wqkv * prenorm_g), row sums ----------------
__global__ void prep_w_kernel(const float* __restrict__ W, const float* __restrict__ g)
{
    int warp = (blockIdx.x * blockDim.x + threadIdx.x) >> 5;
    int lane = threadIdx.x & 31;
    if (warp >= QKVROWS) return;
    float s = 0.f;
    for (int c = lane; c < DIMC; c += 32) {
        float w = __half2float(__float2half_rn(W[warp * DIMC + c] * g[c]));
        g_Wg[warp * DIMC + c] = w;
        s += w;
    }
    #pragma unroll
    for (int o = 16; o > 0; o >>= 1) s += __shfl_down_sync(0xffffffffu, s, o);
    if (lane == 0) g_wsum[warp] = s;
}

// ---------------- channel-LN statistics over C=384 ----------------
template<int MODE>
__global__ void chan_stats_kernel(const float* __restrict__ xarg)
{
    int p = blockIdx.x * blockDim.x + threadIdx.x;
    if (p >= BATCH * NPIX) return;
    const float* src = (MODE == 0) ? xarg : g_y;
    const float* base = src + (size_t)(p >> 12) * DIMC * NPIX + (p & (NPIX - 1));
    float s = 0.f, s2 = 0.f;
    #pragma unroll 4
    for (int c = 0; c < DIMC; c++) {
        float v = base[(size_t)c * NPIX];
        s += v; s2 += v * v;
    }
    float m   = s * (1.f / DIMC);
    float var = s2 * (1.f / DIMC) - m * m;
    float r   = rsqrtf(var + 1e-5f);
    if (MODE == 0) { g_mean[p]  = m; g_rstd[p]  = r; }
    else           { g_mean2[p] = m; g_rstd2[p] = r; }
}

// =======================================================================
// fp16 tensor-core GEMM (fp32 accum): 128x128x16, 256 thr (8 warps 4x2),
// warp tile 32x64, mma.sync.m16n8k16, register-staged pipeline.
// KIND 0: qkv(h) = rstd*(Wg@x - mean*wsum)   A=g_Wg      B=x f32    C=g_qkvh
// KIND 1: y(f32) = Wout@attn + bout          A=Wout(arg) B=g_attnh  C=g_y
// KIND 2: attn(h)= ctxT@q (per b,h)          A=g_ctxT    B=g_qkvh   C=g_attnh
// =======================================================================
#define BM 128
#define BN 128
#define BK 16
#define PADH 4          // smem k-stride = 20 halves (40B)

template<int KIND, int M, int K>
__global__ __launch_bounds__(256, 2)
void h16gemm_kernel(const float* __restrict__ Aext, const float* __restrict__ Bext,
                    const float* __restrict__ bias)
{
    const int N = NPIX;
    constexpr bool HALF_B = (KIND != 0);
    constexpr bool HALF_C = (KIND != 1);
    __shared__ __half As[BM][BK + PADH];   // [m][k]
    __shared__ __half Bs[BN][BK + PADH];   // [n][k]

    int z = blockIdx.z;
    const float* A; const float* Bf = nullptr; const __half* Bh = nullptr;
    float* Cf = nullptr; __half* Ch = nullptr;
    const float* mean = nullptr; const float* rstd = nullptr;

    if (KIND == 0) {
        A  = g_Wg;
        Bf = Bext + (size_t)z * K * N;
        Ch = g_qkvh + (size_t)z * M * N;
        mean = g_mean + (size_t)z * N;
        rstd = g_rstd + (size_t)z * N;
    } else if (KIND == 1) {
        A  = Aext;
        Bh = g_attnh + (size_t)z * K * N;
        Cf = g_y + (size_t)z * M * N;
    } else { // KIND == 2
        int b = z >> 2, h = z & 3;
        A  = g_ctxT + (size_t)z * CH * CH;
        Bh = g_qkvh + ((size_t)b * QKVROWS + h * CH) * N;   // q region
        Ch = g_attnh + ((size_t)b * DIMC + h * CH) * N;
    }

    int tid  = threadIdx.x;
    int lane = tid & 31;
    int wid  = tid >> 5;
    int warpM = wid & 3;
    int warpN = wid >> 2;
    int gid = lane >> 2;
    int tig = lane & 3;

    int rowBase = blockIdx.y * BM;
    int colBase = blockIdx.x * BN;

    // B-load coords
    int tn  = tid & 127;            // float-B path
    int kg  = tid >> 7;             // 0..1
    int tn2 = (tid & 63) << 1;      // half-B path: 2 columns
    int kg4 = tid >> 6;             // 0..3 -> 4 k rows each

    float acc[2][8][4];
    #pragma unroll
    for (int i = 0; i < 2; i++)
        #pragma unroll
        for (int j = 0; j < 8; j++)
            #pragma unroll
            for (int t = 0; t < 4; t++) acc[i][j][t] = 0.f;

    float4  aReg[2];
    float   bReg[8];
    __half2 bRegH[4];

    // prologue: stage K-tile 0
    #pragma unroll
    for (int i = 0; i < 2; i++) {
        int idx = tid + i * 256;
        int r   = idx >> 2;
        int c4  = (idx & 3) << 2;
        int gr  = rowBase + r;
        aReg[i] = (gr < M) ? *(const float4*)&A[(size_t)gr * K + c4]
                           : make_float4(0.f, 0.f, 0.f, 0.f);
    }
    if (HALF_B) {
        #pragma unroll
        for (int j = 0; j < 4; j++)
            bRegH[j] = *(const __half2*)&Bh[(size_t)(kg4 * 4 + j) * N + colBase + tn2];
    } else {
        #pragma unroll
        for (int j = 0; j < 8; j++)
            bReg[j] = Bf[(size_t)(kg * 8 + j) * N + colBase + tn];
    }

    for (int k0 = 0; k0 < K; k0 += BK) {
        // commit staged registers -> smem halves
        #pragma unroll
        for (int i = 0; i < 2; i++) {
            int idx = tid + i * 256;
            int r   = idx >> 2;
            int c4  = (idx & 3) << 2;
            *(half2*)&As[r][c4]     = __floats2half2_rn(aReg[i].x, aReg[i].y);
            *(half2*)&As[r][c4 + 2] = __floats2half2_rn(aReg[i].z, aReg[i].w);
        }
        if (HALF_B) {
            #pragma unroll
            for (int j = 0; j < 4; j++) {
                Bs[tn2    ][kg4 * 4 + j] = __low2half(bRegH[j]);
                Bs[tn2 + 1][kg4 * 4 + j] = __high2half(bRegH[j]);
            }
        } else {
            #pragma unroll
            for (int j = 0; j < 4; j++)
                *(half2*)&Bs[tn][kg * 8 + 2 * j] = __floats2half2_rn(bReg[2 * j], bReg[2 * j + 1]);
        }
        __syncthreads();

        // prefetch next K-tile
        int k1 = k0 + BK;
        if (k1 < K) {
            #pragma unroll
            for (int i = 0; i < 2; i++) {
                int idx = tid + i * 256;
                int r   = idx >> 2;
                int c4  = (idx & 3) << 2;
                int gr  = rowBase + r;
                aReg[i] = (gr < M) ? *(const float4*)&A[(size_t)gr * K + k1 + c4]
                                   : make_float4(0.f, 0.f, 0.f, 0.f);
            }
            if (HALF_B) {
                #pragma unroll
                for (int j = 0; j < 4; j++)
                    bRegH[j] = *(const __half2*)&Bh[(size_t)(k1 + kg4 * 4 + j) * N + colBase + tn2];
            } else {
                #pragma unroll
                for (int j = 0; j < 8; j++)
                    bReg[j] = Bf[(size_t)(k1 + kg * 8 + j) * N + colBase + tn];
            }
        }

        // fragments + MMA
        unsigned af[2][4];
        #pragma unroll
        for (int i = 0; i < 2; i++) {
            int mr = warpM * 32 + i * 16 + gid;
            af[i][0] = *(const unsigned*)&As[mr    ][2 * tig];
            af[i][1] = *(const unsigned*)&As[mr + 8][2 * tig];
            af[i][2] = *(const unsigned*)&As[mr    ][2 * tig + 8];
            af[i][3] = *(const unsigned*)&As[mr + 8][2 * tig + 8];
        }
        unsigned bf[8][2];
        #pragma unroll
        for (int j = 0; j < 8; j++) {
            int nc = warpN * 64 + j * 8 + gid;
            bf[j][0] = *(const unsigned*)&Bs[nc][2 * tig];
            bf[j][1] = *(const unsigned*)&Bs[nc][2 * tig + 8];
        }
        #pragma unroll
        for (int i = 0; i < 2; i++)
            #pragma unroll
            for (int j = 0; j < 8; j++) {
                asm volatile(
                    "mma.sync.aligned.m16n8k16.row.col.f32.f16.f16.f32 "
                    "{%0,%1,%2,%3},{%4,%5,%6,%7},{%8,%9},{%0,%1,%2,%3};\n"
                    : "+f"(acc[i][j][0]), "+f"(acc[i][j][1]),
                      "+f"(acc[i][j][2]), "+f"(acc[i][j][3])
                    : "r"(af[i][0]), "r"(af[i][1]), "r"(af[i][2]), "r"(af[i][3]),
                      "r"(bf[j][0]), "r"(bf[j][1]));
            }
        __syncthreads();
    }

    // ---------------- epilogue ----------------
    #pragma unroll
    for (int i = 0; i < 2; i++) {
        int r0 = rowBase + warpM * 32 + i * 16 + gid;
        int r1 = r0 + 8;
        float w0 = 0.f, w1 = 0.f, bb0 = 0.f, bb1 = 0.f;
        if (KIND == 0)      { w0 = g_wsum[r0]; w1 = g_wsum[r1]; }
        else if (KIND == 1) { bb0 = bias[r0];  bb1 = bias[r1]; }
        #pragma unroll
        for (int j = 0; j < 8; j++) {
            int c0 = colBase + warpN * 64 + j * 8 + 2 * tig;
            if (KIND == 0) {
                float m0 = mean[c0], m1 = mean[c0 + 1];
                float v0 = rstd[c0], v1 = rstd[c0 + 1];
                *(half2*)&Ch[(size_t)r0 * N + c0] =
                    __floats2half2_rn(v0 * (acc[i][j][0] - m0 * w0),
                                      v1 * (acc[i][j][1] - m1 * w0));
                *(half2*)&Ch[(size_t)r1 * N + c0] =
                    __floats2half2_rn(v0 * (acc[i][j][2] - m0 * w1),
                                      v1 * (acc[i][j][3] - m1 * w1));
            } else if (KIND == 1) {
                *(float2*)&Cf[(size_t)r0 * N + c0] =
                    make_float2(acc[i][j][0] + bb0, acc[i][j][1] + bb0);
                *(float2*)&Cf[(size_t)r1 * N + c0] =
                    make_float2(acc[i][j][2] + bb1, acc[i][j][3] + bb1);
            } else {
                if (r0 < M)
                    *(half2*)&Ch[(size_t)r0 * N + c0] =
                        __floats2half2_rn(acc[i][j][0], acc[i][j][1]);
                if (r1 < M)
                    *(half2*)&Ch[(size_t)r1 * N + c0] =
                        __floats2half2_rn(acc[i][j][2], acc[i][j][3]);
            }
        }
    }
}

// ---------------- q softmax over channel dim (96) per (b,h,pixel), fp16 io ----------------
__global__ __launch_bounds__(128) void q_softmax_kernel()
{
    int idx = blockIdx.x * blockDim.x + threadIdx.x;
    if (idx >= BATCH * HEADS * NPIX) return;
    int pix = idx & 4095;
    int h   = (idx >> 12) & 3;
    int b   = idx >> 14;
    __half* base = g_qkvh + ((size_t)b * QKVROWS + h * CH) * NPIX + pix;

    float v[CH];
    float mx = -1e30f;
    #pragma unroll
    for (int d = 0; d < CH; d++) {
        v[d] = __half2float(base[(size_t)d * NPIX]);
        mx = fmaxf(mx, v[d]);
    }
    float s = 0.f;
    #pragma unroll
    for (int d = 0; d < CH; d++) {
        v[d] = __expf(v[d] - mx);
        s += v[d];
    }
    float inv = QSCALE / s;
    #pragma unroll
    for (int d = 0; d < CH; d++) base[(size_t)d * NPIX] = __float2half_rn(v[d] * inv);
}

// ---------------- k softmax over spatial dim (4096) per (b, channel), fp16 io ----------------
__global__ __launch_bounds__(256) void k_softmax_kernel()
{
    int row = blockIdx.x;
    int b = row / DIMC, r = row % DIMC;
    __half* base = g_qkvh + ((size_t)b * QKVROWS + DIMC + r) * NPIX;
    int tid  = threadIdx.x;
    int lane = tid & 31, warp = tid >> 5;

    // 4096 halves / 256 threads = 16 halves/thread = 2 x uint4
    float f[16];
    float mx = -1e30f;
    #pragma unroll
    for (int j = 0; j < 2; j++) {
        uint4 u = *(const uint4*)&base[(size_t)(j * 256 + tid) * 8];
        const __half2* hp = (const __half2*)&u;
        #pragma unroll
        for (int t = 0; t < 4; t++) {
            float2 p = __half22float2(hp[t]);
            f[j * 8 + 2 * t]     = p.x;
            f[j * 8 + 2 * t + 1] = p.y;
            mx = fmaxf(mx, fmaxf(p.x, p.y));
        }
    }
    __shared__ float smax[8];
    __shared__ float ssum[8];
    #pragma unroll
    for (int o = 16; o > 0; o >>= 1) mx = fmaxf(mx, __shfl_xor_sync(0xffffffffu, mx, o));
    if (lane == 0) smax[warp] = mx;
    __syncthreads();
    mx = smax[0];
    #pragma unroll
    for (int w = 1; w < 8; w++) mx = fmaxf(mx, smax[w]);

    float s = 0.f;
    #pragma unroll
    for (int t = 0; t < 16; t++) {
        f[t] = __expf(f[t] - mx);
        s += f[t];
    }
    #pragma unroll
    for (int o = 16; o > 0; o >>= 1) s += __shfl_xor_sync(0xffffffffu, s, o);
    if (lane == 0) ssum[warp] = s;
    __syncthreads();
    s = 0.f;
    #pragma unroll
    for (int w = 0; w < 8; w++) s += ssum[w];

    float inv = 1.f / s;
    #pragma unroll
    for (int j = 0; j < 2; j++) {
        uint4 u;
        __half2* hp = (__half2*)&u;
        #pragma unroll
        for (int t = 0; t < 4; t++)
            hp[t] = __floats2half2_rn(f[j * 8 + 2 * t] * inv, f[j * 8 + 2 * t + 1] * inv);
        *(uint4*)&base[(size_t)(j * 256 + tid) * 8] = u;
    }
}

// ---------------- zero ctx accumulator ----------------
__global__ void zero_ctx_kernel()
{
    int i = blockIdx.x * blockDim.x + threadIdx.x;
    if (i < BATCH * HEADS * CH * CH) g_ctxT[i] = 0.f;
}

// =======================================================================
// ctx via tf32 MMA: ctxT[e][d] = sum_n v[e,n]*k[d,n], fp16 inputs (exact in tf32)
// =======================================================================
__global__ __launch_bounds__(256)
void ctx_tf32_kernel()
{
    int sk = blockIdx.x;
    int bh = blockIdx.y;
    int b = bh >> 2, h = bh & 3;
    const __half* kb = g_qkvh + ((size_t)b * QKVROWS + DIMC     + h * CH) * NPIX;
    const __half* vb = g_qkvh + ((size_t)b * QKVROWS + 2 * DIMC + h * CH) * NPIX;

    __shared__ float As[BK][CH + 4];
    __shared__ float Bs[BK][CH + 4];

    int tid  = threadIdx.x;
    int lane = tid & 31;
    int wid  = tid >> 5;
    int warpM = wid & 1;
    int warpN = wid >> 1;
    int gid = lane >> 2;
    int tig = lane & 3;

    float acc[3][3][4];
    #pragma unroll
    for (int i = 0; i < 3; i++)
        #pragma unroll
        for (int j = 0; j < 3; j++)
            #pragma unroll
            for (int t = 0; t < 4; t++) acc[i][j][t] = 0.f;

    const int KLEN = NPIX / CTX_SPLIT;
    int n0 = sk * KLEN;

    for (int nt = 0; nt < KLEN; nt += BK) {
        #pragma unroll
        for (int i = 0; i < 2; i++) {
            int idx = tid + i * 256;
            if (idx < 384) {
                int r  = idx >> 2;
                int c4 = (idx & 3) << 2;
                const __half2* pv = (const __half2*)&vb[(size_t)r * NPIX + n0 + nt + c4];
                float2 v0 = __half22float2(pv[0]);
                float2 v1 = __half22float2(pv[1]);
                As[c4 + 0][r] = v0.x; As[c4 + 1][r] = v0.y;
                As[c4 + 2][r] = v1.x; As[c4 + 3][r] = v1.y;
                const __half2* pk = (const __half2*)&kb[(size_t)r * NPIX + n0 + nt + c4];
                float2 k0 = __half22float2(pk[0]);
                float2 k1 = __half22float2(pk[1]);
                Bs[c4 + 0][r] = k0.x; Bs[c4 + 1][r] = k0.y;
                Bs[c4 + 2][r] = k1.x; Bs[c4 + 3][r] = k1.y;
            }
        }
        __syncthreads();

        #pragma unroll
        for (int ks = 0; ks < 2; ks++) {
            int kb8 = ks * 8;
            unsigned af[3][4];
            #pragma unroll
            for (int i = 0; i < 3; i++) {
                int mr = warpM * 48 + i * 16 + gid;
                af[i][0] = __float_as_uint(As[kb8 + tig    ][mr]);
                af[i][1] = __float_as_uint(As[kb8 + tig    ][mr + 8]);
                af[i][2] = __float_as_uint(As[kb8 + tig + 4][mr]);
                af[i][3] = __float_as_uint(As[kb8 + tig + 4][mr + 8]);
            }
            unsigned bf[3][2];
            #pragma unroll
            for (int j = 0; j < 3; j++) {
                int nc = warpN * 24 + j * 8 + gid;
                bf[j][0] = __float_as_uint(Bs[kb8 + tig    ][nc]);
                bf[j][1] = __float_as_uint(Bs[kb8 + tig + 4][nc]);
            }
            #pragma unroll
            for (int i = 0; i < 3; i++)
                #pragma unroll
                for (int j = 0; j < 3; j++) {
                    asm volatile(
                        "mma.sync.aligned.m16n8k8.row.col.f32.tf32.tf32.f32 "
                        "{%0,%1,%2,%3},{%4,%5,%6,%7},{%8,%9},{%0,%1,%2,%3};\n"
                        : "+f"(acc[i][j][0]), "+f"(acc[i][j][1]),
                          "+f"(acc[i][j][2]), "+f"(acc[i][j][3])
                        : "r"(af[i][0]), "r"(af[i][1]), "r"(af[i][2]), "r"(af[i][3]),
                          "r"(bf[j][0]), "r"(bf[j][1]));
                }
        }
        __syncthreads();
    }

    float* cb = g_ctxT + (size_t)bh * CH * CH;
    #pragma unroll
    for (int i = 0; i < 3; i++) {
        int e0 = warpM * 48 + i * 16 + gid;
        int e1 = e0 + 8;
        #pragma unroll
        for (int j = 0; j < 3; j++) {
            int d0 = warpN * 24 + j * 8 + 2 * tig;
            atomicAdd(&cb[e0 * CH + d0    ], acc[i][j][0]);
            atomicAdd(&cb[e0 * CH + d0 + 1], acc[i][j][1]);
            atomicAdd(&cb[e1 * CH + d0    ], acc[i][j][2]);
            atomicAdd(&cb[e1 * CH + d0 + 1], acc[i][j][3]);
        }
    }
}

// ---------------- final: LN(y)*outg + (x-mean)*rstd*preg ----------------
__global__ void final_kernel(const float* __restrict__ x, const float* __restrict__ preg,
                             const float* __restrict__ outg, float* __restrict__ out)
{
    size_t i = (size_t)blockIdx.x * blockDim.x + threadIdx.x;
    if (i >= (size_t)BATCH * DIMC * NPIX) return;
    int pix = (int)(i & 4095);
    int bc  = (int)(i >> 12);
    int c   = bc % DIMC;
    int b   = bc / DIMC;
    int bp  = b * NPIX + pix;
    float xn = (x[i]   - g_mean[bp])  * g_rstd[bp]  * preg[c];
    float yn = (g_y[i] - g_mean2[bp]) * g_rstd2[bp] * outg[c];
    out[i] = yn + xn;
}

// ---------------- launch ----------------
extern "C" void kernel_launch(void* const* d_in, const int* in_sizes, int n_in,
                              void* d_out, int out_size)
{
    const float* x    = (const float*)d_in[0];
    const float* preg = (const float*)d_in[1];
    const float* Wqkv = (const float*)d_in[2];
    const float* Wout = (const float*)d_in[3];
    const float* bout = (const float*)d_in[4];
    const float* outg = (const float*)d_in[5];
    float* out = (float*)d_out;
    (void)in_sizes; (void)n_in; (void)out_size;

    // 1. prep folded (fp16-rounded) weights + prenorm stats
    prep_w_kernel<<<(QKVROWS * 32 + 255) / 256, 256>>>(Wqkv, preg);
    chan_stats_kernel<0><<<(BATCH * NPIX) / 256, 256>>>(x);

    // 2. QKV GEMM (fp16 MMA) with LN folded; fp16 output
    h16gemm_kernel<0, QKVROWS, DIMC><<<dim3(NPIX / BN, QKVROWS / BM, BATCH), 256>>>(nullptr, x, nullptr);

    // 3. softmaxes (in place, fp16)
    q_softmax_kernel<<<(BATCH * HEADS * NPIX) / 128, 128>>>();
    k_softmax_kernel<<<BATCH * DIMC, 256>>>();

    // 4. context (tf32 MMA over fp16 inputs) and apply to q (fp16 MMA)
    zero_ctx_kernel<<<(BATCH * HEADS * CH * CH + 255) / 256, 256>>>();
    ctx_tf32_kernel<<<dim3(CTX_SPLIT, BATCH * HEADS), 256>>>();
    h16gemm_kernel<2, CH, CH><<<dim3(NPIX / BN, 1, BATCH * HEADS), 256>>>(nullptr, nullptr, nullptr);

    // 5. out projection + bias (fp16 MMA, fp32 out)
    h16gemm_kernel<1, DIMC, DIMC><<<dim3(NPIX / BN, DIMC / BM, BATCH), 256>>>(Wout, nullptr, bout);

    // 6. out-LN stats + fused LN/residual epilogue
    chan_stats_kernel<1><<<(BATCH * NPIX) / 256, 256>>>(nullptr);
    final_kernel<<<(int)(((size_t)BATCH * DIMC * NPIX + 255) / 256), 256>>>(x, preg, outg, out);
}

// round 8
// speedup vs baseline: 1.0619x; 1.0619x over previous
#include <cuda_runtime.h>
#include <cuda_fp16.h>
#include <math.h>

// ---------------- problem constants ----------------
#define DIMC   384
#define NPIX   4096
#define BATCH  16
#define HEADS  4
#define CH     96
#define QKVROWS 1152
#define QSCALE 0.1020620726159658f   // 96^-0.5
#define CTX_SPLIT 8

// ---------------- scratch (device globals; allocation-free contract) ----------------
__device__ float  g_Wg[QKVROWS * DIMC];
__device__ float  g_wsum[QKVROWS];
__device__ float  g_mean[BATCH * NPIX];
__device__ float  g_rstd[BATCH * NPIX];
__device__ float  g_mean2[BATCH * NPIX];
__device__ float  g_rstd2[BATCH * NPIX];
__device__ __half g_qkvh[(size_t)BATCH * QKVROWS * NPIX];   // 151 MB, fp16
__device__ float  g_ctxT[BATCH * HEADS * CH * CH];          // ctx^T: [bh][e][d]
__device__ __half g_attnh[(size_t)BATCH * DIMC * NPIX];     // 50 MB, fp16
__device__ float  g_y[(size_t)BATCH * DIMC * NPIX];         // 100 MB

// ---------------- prep: W' = fp16-rounded(Wqkv * prenorm_g), row sums ----------------
__global__ void prep_w_kernel(const float* __restrict__ W, const float* __restrict__ g)
{
    int warp = (blockIdx.x * blockDim.x + threadIdx.x) >> 5;
    int lane = threadIdx.x & 31;
    if (warp >= QKVROWS) return;
    float s = 0.f;
    for (int c = lane; c < DIMC; c += 32) {
        float w = __half2float(__float2half_rn(W[warp * DIMC + c] * g[c]));
        g_Wg[warp * DIMC + c] = w;
        s += w;
    }
    #pragma unroll
    for (int o = 16; o > 0; o >>= 1) s += __shfl_down_sync(0xffffffffu, s, o);
    if (lane == 0) g_wsum[warp] = s;
}

// ---------------- channel-LN statistics over C=384 (out-LN only) ----------------
__global__ void chan_stats2_kernel()
{
    int p = blockIdx.x * blockDim.x + threadIdx.x;
    if (p >= BATCH * NPIX) return;
    const float* base = g_y + (size_t)(p >> 12) * DIMC * NPIX + (p & (NPIX - 1));
    float s = 0.f, s2 = 0.f;
    #pragma unroll 4
    for (int c = 0; c < DIMC; c++) {
        float v = base[(size_t)c * NPIX];
        s += v; s2 += v * v;
    }
    float m   = s * (1.f / DIMC);
    float var = s2 * (1.f / DIMC) - m * m;
    g_mean2[p] = m;
    g_rstd2[p] = rsqrtf(var + 1e-5f);
}

// =======================================================================
// fp16 tensor-core GEMM (fp32 accum): 128x128x16, 256 thr (8 warps 4x2),
// warp tile 32x64, mma.sync.m16n8k16, DOUBLE-BUFFERED smem (1 sync/iter).
// KIND 0: qkv(h) = rstd*(Wg@x - mean*wsum)   A=g_Wg      B=x f32    C=g_qkvh
//         + fused prenorm stats (block-local from B loads; y==0 publishes)
// KIND 1: y(f32) = Wout@attn + bout          A=Wout(arg) B=g_attnh  C=g_y
// KIND 2: attn(h)= ctxT@q (per b,h)          A=g_ctxT    B=g_qkvh   C=g_attnh
// =======================================================================
#define BM 128
#define BN 128
#define BK 16
#define PADH 4          // smem k-stride = 20 halves (40B)

template<int KIND, int M, int K>
__global__ __launch_bounds__(256, 2)
void h16gemm_kernel(const float* __restrict__ Aext, const float* __restrict__ Bext,
                    const float* __restrict__ bias)
{
    const int N = NPIX;
    constexpr bool HALF_B = (KIND != 0);
    __shared__ __half As[2][BM][BK + PADH];   // [stage][m][k]
    __shared__ __half Bs[2][BN][BK + PADH];   // [stage][n][k]
    __shared__ float  sred[256], sred2[256];
    __shared__ float  meanS[BN], rstdS[BN];

    int z = blockIdx.z;
    const float* A; const float* Bf = nullptr; const __half* Bh = nullptr;
    float* Cf = nullptr; __half* Ch = nullptr;

    if (KIND == 0) {
        A  = g_Wg;
        Bf = Bext + (size_t)z * K * N;
        Ch = g_qkvh + (size_t)z * M * N;
    } else if (KIND == 1) {
        A  = Aext;
        Bh = g_attnh + (size_t)z * K * N;
        Cf = g_y + (size_t)z * M * N;
    } else { // KIND == 2
        int b = z >> 2, h = z & 3;
        A  = g_ctxT + (size_t)z * CH * CH;
        Bh = g_qkvh + ((size_t)b * QKVROWS + h * CH) * N;   // q region
        Ch = g_attnh + ((size_t)b * DIMC + h * CH) * N;
    }

    int tid  = threadIdx.x;
    int lane = tid & 31;
    int wid  = tid >> 5;
    int warpM = wid & 3;
    int warpN = wid >> 2;
    int gid = lane >> 2;
    int tig = lane & 3;

    int rowBase = blockIdx.y * BM;
    int colBase = blockIdx.x * BN;

    // B-load coords
    int tn  = tid & 127;            // float-B path: one column per thread
    int kg  = tid >> 7;             // 0..1 -> 8 k rows each
    int tn2 = (tid & 63) << 1;      // half-B path: 2 columns
    int kg4 = tid >> 6;             // 0..3 -> 4 k rows each

    float acc[2][8][4];
    #pragma unroll
    for (int i = 0; i < 2; i++)
        #pragma unroll
        for (int j = 0; j < 8; j++)
            #pragma unroll
            for (int t = 0; t < 4; t++) acc[i][j][t] = 0.f;

    float4  aReg[2];
    float   bReg[8];
    __half2 bRegH[4];
    float   statS = 0.f, statS2 = 0.f;   // KIND 0: per-column partial sums

    const int NT = K / BK;

    // ---- stage tile 0 ----
    #pragma unroll
    for (int i = 0; i < 2; i++) {
        int idx = tid + i * 256;
        int r   = idx >> 2;
        int c4  = (idx & 3) << 2;
        int gr  = rowBase + r;
        aReg[i] = (gr < M) ? *(const float4*)&A[(size_t)gr * K + c4]
                           : make_float4(0.f, 0.f, 0.f, 0.f);
    }
    if (HALF_B) {
        #pragma unroll
        for (int j = 0; j < 4; j++)
            bRegH[j] = *(const __half2*)&Bh[(size_t)(kg4 * 4 + j) * N + colBase + tn2];
    } else {
        #pragma unroll
        for (int j = 0; j < 8; j++)
            bReg[j] = Bf[(size_t)(kg * 8 + j) * N + colBase + tn];
    }

    // ---- commit tile 0 into stage 0 ----
    #pragma unroll
    for (int i = 0; i < 2; i++) {
        int idx = tid + i * 256;
        int r   = idx >> 2;
        int c4  = (idx & 3) << 2;
        *(half2*)&As[0][r][c4]     = __floats2half2_rn(aReg[i].x, aReg[i].y);
        *(half2*)&As[0][r][c4 + 2] = __floats2half2_rn(aReg[i].z, aReg[i].w);
    }
    if (HALF_B) {
        #pragma unroll
        for (int j = 0; j < 4; j++) {
            Bs[0][tn2    ][kg4 * 4 + j] = __low2half(bRegH[j]);
            Bs[0][tn2 + 1][kg4 * 4 + j] = __high2half(bRegH[j]);
        }
    } else {
        #pragma unroll
        for (int j = 0; j < 4; j++)
            *(half2*)&Bs[0][tn][kg * 8 + 2 * j] = __floats2half2_rn(bReg[2 * j], bReg[2 * j + 1]);
        if (KIND == 0) {
            #pragma unroll
            for (int j = 0; j < 8; j++) { statS += bReg[j]; statS2 += bReg[j] * bReg[j]; }
        }
    }
    __syncthreads();

    // ---- mainloop: 1 sync per iteration ----
    for (int kt = 0; kt < NT; kt++) {
        int cur = kt & 1;
        bool hasNext = (kt + 1 < NT);

        // stage tile kt+1 (LDG issued before MMAs -> latency hidden)
        if (hasNext) {
            int k1 = (kt + 1) * BK;
            #pragma unroll
            for (int i = 0; i < 2; i++) {
                int idx = tid + i * 256;
                int r   = idx >> 2;
                int c4  = (idx & 3) << 2;
                int gr  = rowBase + r;
                aReg[i] = (gr < M) ? *(const float4*)&A[(size_t)gr * K + k1 + c4]
                                   : make_float4(0.f, 0.f, 0.f, 0.f);
            }
            if (HALF_B) {
                #pragma unroll
                for (int j = 0; j < 4; j++)
                    bRegH[j] = *(const __half2*)&Bh[(size_t)(k1 + kg4 * 4 + j) * N + colBase + tn2];
            } else {
                #pragma unroll
                for (int j = 0; j < 8; j++)
                    bReg[j] = Bf[(size_t)(k1 + kg * 8 + j) * N + colBase + tn];
            }
        }

        // fragments + MMA on buf[cur]
        unsigned af[2][4];
        #pragma unroll
        for (int i = 0; i < 2; i++) {
            int mr = warpM * 32 + i * 16 + gid;
            af[i][0] = *(const unsigned*)&As[cur][mr    ][2 * tig];
            af[i][1] = *(const unsigned*)&As[cur][mr + 8][2 * tig];
            af[i][2] = *(const unsigned*)&As[cur][mr    ][2 * tig + 8];
            af[i][3] = *(const unsigned*)&As[cur][mr + 8][2 * tig + 8];
        }
        unsigned bf[8][2];
        #pragma unroll
        for (int j = 0; j < 8; j++) {
            int nc = warpN * 64 + j * 8 + gid;
            bf[j][0] = *(const unsigned*)&Bs[cur][nc][2 * tig];
            bf[j][1] = *(const unsigned*)&Bs[cur][nc][2 * tig + 8];
        }
        #pragma unroll
        for (int i = 0; i < 2; i++)
            #pragma unroll
            for (int j = 0; j < 8; j++) {
                asm volatile(
                    "mma.sync.aligned.m16n8k16.row.col.f32.f16.f16.f32 "
                    "{%0,%1,%2,%3},{%4,%5,%6,%7},{%8,%9},{%0,%1,%2,%3};\n"
                    : "+f"(acc[i][j][0]), "+f"(acc[i][j][1]),
                      "+f"(acc[i][j][2]), "+f"(acc[i][j][3])
                    : "r"(af[i][0]), "r"(af[i][1]), "r"(af[i][2]), "r"(af[i][3]),
                      "r"(bf[j][0]), "r"(bf[j][1]));
            }

        // commit staged tile into the other buffer
        if (hasNext) {
            int nxt = cur ^ 1;
            #pragma unroll
            for (int i = 0; i < 2; i++) {
                int idx = tid + i * 256;
                int r   = idx >> 2;
                int c4  = (idx & 3) << 2;
                *(half2*)&As[nxt][r][c4]     = __floats2half2_rn(aReg[i].x, aReg[i].y);
                *(half2*)&As[nxt][r][c4 + 2] = __floats2half2_rn(aReg[i].z, aReg[i].w);
            }
            if (HALF_B) {
                #pragma unroll
                for (int j = 0; j < 4; j++) {
                    Bs[nxt][tn2    ][kg4 * 4 + j] = __low2half(bRegH[j]);
                    Bs[nxt][tn2 + 1][kg4 * 4 + j] = __high2half(bRegH[j]);
                }
            } else {
                #pragma unroll
                for (int j = 0; j < 4; j++)
                    *(half2*)&Bs[nxt][tn][kg * 8 + 2 * j] =
                        __floats2half2_rn(bReg[2 * j], bReg[2 * j + 1]);
                if (KIND == 0) {
                    #pragma unroll
                    for (int j = 0; j < 8; j++) { statS += bReg[j]; statS2 += bReg[j] * bReg[j]; }
                }
            }
        }
        __syncthreads();
    }

    // ---- KIND 0: block-local LN stats (each column fully covered by 2 threads) ----
    if (KIND == 0) {
        sred[tid] = statS; sred2[tid] = statS2;
        __syncthreads();
        if (tid < 128) {
            float st  = sred[tid]  + sred[tid + 128];
            float s2t = sred2[tid] + sred2[tid + 128];
            float m   = st * (1.f / DIMC);
            float var = s2t * (1.f / DIMC) - m * m;
            float r   = rsqrtf(var + 1e-5f);
            meanS[tid] = m; rstdS[tid] = r;
            if (blockIdx.y == 0) {
                g_mean[(size_t)z * NPIX + colBase + tid] = m;
                g_rstd[(size_t)z * NPIX + colBase + tid] = r;
            }
        }
        __syncthreads();
    }

    // ---------------- epilogue ----------------
    #pragma unroll
    for (int i = 0; i < 2; i++) {
        int r0 = rowBase + warpM * 32 + i * 16 + gid;
        int r1 = r0 + 8;
        float w0 = 0.f, w1 = 0.f, bb0 = 0.f, bb1 = 0.f;
        if (KIND == 0)      { w0 = g_wsum[r0]; w1 = g_wsum[r1]; }
        else if (KIND == 1) { bb0 = bias[r0];  bb1 = bias[r1]; }
        #pragma unroll
        for (int j = 0; j < 8; j++) {
            int cc = warpN * 64 + j * 8 + 2 * tig;   // block-local column
            int c0 = colBase + cc;
            if (KIND == 0) {
                float m0 = meanS[cc], m1 = meanS[cc + 1];
                float v0 = rstdS[cc], v1 = rstdS[cc + 1];
                *(half2*)&Ch[(size_t)r0 * N + c0] =
                    __floats2half2_rn(v0 * (acc[i][j][0] - m0 * w0),
                                      v1 * (acc[i][j][1] - m1 * w0));
                *(half2*)&Ch[(size_t)r1 * N + c0] =
                    __floats2half2_rn(v0 * (acc[i][j][2] - m0 * w1),
                                      v1 * (acc[i][j][3] - m1 * w1));
            } else if (KIND == 1) {
                *(float2*)&Cf[(size_t)r0 * N + c0] =
                    make_float2(acc[i][j][0] + bb0, acc[i][j][1] + bb0);
                *(float2*)&Cf[(size_t)r1 * N + c0] =
                    make_float2(acc[i][j][2] + bb1, acc[i][j][3] + bb1);
            } else {
                if (r0 < M)
                    *(half2*)&Ch[(size_t)r0 * N + c0] =
                        __floats2half2_rn(acc[i][j][0], acc[i][j][1]);
                if (r1 < M)
                    *(half2*)&Ch[(size_t)r1 * N + c0] =
                        __floats2half2_rn(acc[i][j][2], acc[i][j][3]);
            }
        }
    }
}

// ---------------- q softmax over channel dim (96) per (b,h,pixel), fp16 io ----------------
__global__ __launch_bounds__(128) void q_softmax_kernel()
{
    int idx = blockIdx.x * blockDim.x + threadIdx.x;
    if (idx >= BATCH * HEADS * NPIX) return;
    int pix = idx & 4095;
    int h   = (idx >> 12) & 3;
    int b   = idx >> 14;
    __half* base = g_qkvh + ((size_t)b * QKVROWS + h * CH) * NPIX + pix;

    float v[CH];
    float mx = -1e30f;
    #pragma unroll
    for (int d = 0; d < CH; d++) {
        v[d] = __half2float(base[(size_t)d * NPIX]);
        mx = fmaxf(mx, v[d]);
    }
    float s = 0.f;
    #pragma unroll
    for (int d = 0; d < CH; d++) {
        v[d] = __expf(v[d] - mx);
        s += v[d];
    }
    float inv = QSCALE / s;
    #pragma unroll
    for (int d = 0; d < CH; d++) base[(size_t)d * NPIX] = __float2half_rn(v[d] * inv);
}

// ---------------- k softmax over spatial dim (4096) per (b, channel), fp16 io ----------------
__global__ __launch_bounds__(256) void k_softmax_kernel()
{
    int row = blockIdx.x;
    int b = row / DIMC, r = row % DIMC;
    __half* base = g_qkvh + ((size_t)b * QKVROWS + DIMC + r) * NPIX;
    int tid  = threadIdx.x;
    int lane = tid & 31, warp = tid >> 5;

    float f[16];
    float mx = -1e30f;
    #pragma unroll
    for (int j = 0; j < 2; j++) {
        uint4 u = *(const uint4*)&base[(size_t)(j * 256 + tid) * 8];
        const __half2* hp = (const __half2*)&u;
        #pragma unroll
        for (int t = 0; t < 4; t++) {
            float2 p = __half22float2(hp[t]);
            f[j * 8 + 2 * t]     = p.x;
            f[j * 8 + 2 * t + 1] = p.y;
            mx = fmaxf(mx, fmaxf(p.x, p.y));
        }
    }
    __shared__ float smax[8];
    __shared__ float ssum[8];
    #pragma unroll
    for (int o = 16; o > 0; o >>= 1) mx = fmaxf(mx, __shfl_xor_sync(0xffffffffu, mx, o));
    if (lane == 0) smax[warp] = mx;
    __syncthreads();
    mx = smax[0];
    #pragma unroll
    for (int w = 1; w < 8; w++) mx = fmaxf(mx, smax[w]);

    float s = 0.f;
    #pragma unroll
    for (int t = 0; t < 16; t++) {
        f[t] = __expf(f[t] - mx);
        s += f[t];
    }
    #pragma unroll
    for (int o = 16; o > 0; o >>= 1) s += __shfl_xor_sync(0xffffffffu, s, o);
    if (lane == 0) ssum[warp] = s;
    __syncthreads();
    s = 0.f;
    #pragma unroll
    for (int w = 0; w < 8; w++) s += ssum[w];

    float inv = 1.f / s;
    #pragma unroll
    for (int j = 0; j < 2; j++) {
        uint4 u;
        __half2* hp = (__half2*)&u;
        #pragma unroll
        for (int t = 0; t < 4; t++)
            hp[t] = __floats2half2_rn(f[j * 8 + 2 * t] * inv, f[j * 8 + 2 * t + 1] * inv);
        *(uint4*)&base[(size_t)(j * 256 + tid) * 8] = u;
    }
}

// ---------------- zero ctx accumulator ----------------
__global__ void zero_ctx_kernel()
{
    int i = blockIdx.x * blockDim.x + threadIdx.x;
    if (i < BATCH * HEADS * CH * CH) g_ctxT[i] = 0.f;
}

// =======================================================================
// ctx via tf32 MMA: ctxT[e][d] = sum_n v[e,n]*k[d,n], fp16 inputs
// =======================================================================
#define BKC 16
__global__ __launch_bounds__(256)
void ctx_tf32_kernel()
{
    int sk = blockIdx.x;
    int bh = blockIdx.y;
    int b = bh >> 2, h = bh & 3;
    const __half* kb = g_qkvh + ((size_t)b * QKVROWS + DIMC     + h * CH) * NPIX;
    const __half* vb = g_qkvh + ((size_t)b * QKVROWS + 2 * DIMC + h * CH) * NPIX;

    __shared__ float As[BKC][CH + 4];
    __shared__ float Bs[BKC][CH + 4];

    int tid  = threadIdx.x;
    int lane = tid & 31;
    int wid  = tid >> 5;
    int warpM = wid & 1;
    int warpN = wid >> 1;
    int gid = lane >> 2;
    int tig = lane & 3;

    float acc[3][3][4];
    #pragma unroll
    for (int i = 0; i < 3; i++)
        #pragma unroll
        for (int j = 0; j < 3; j++)
            #pragma unroll
            for (int t = 0; t < 4; t++) acc[i][j][t] = 0.f;

    const int KLEN = NPIX / CTX_SPLIT;
    int n0 = sk * KLEN;

    for (int nt = 0; nt < KLEN; nt += BKC) {
        #pragma unroll
        for (int i = 0; i < 2; i++) {
            int idx = tid + i * 256;
            if (idx < 384) {
                int r  = idx >> 2;
                int c4 = (idx & 3) << 2;
                const __half2* pv = (const __half2*)&vb[(size_t)r * NPIX + n0 + nt + c4];
                float2 v0 = __half22float2(pv[0]);
                float2 v1 = __half22float2(pv[1]);
                As[c4 + 0][r] = v0.x; As[c4 + 1][r] = v0.y;
                As[c4 + 2][r] = v1.x; As[c4 + 3][r] = v1.y;
                const __half2* pk = (const __half2*)&kb[(size_t)r * NPIX + n0 + nt + c4];
                float2 k0 = __half22float2(pk[0]);
                float2 k1 = __half22float2(pk[1]);
                Bs[c4 + 0][r] = k0.x; Bs[c4 + 1][r] = k0.y;
                Bs[c4 + 2][r] = k1.x; Bs[c4 + 3][r] = k1.y;
            }
        }
        __syncthreads();

        #pragma unroll
        for (int ks = 0; ks < 2; ks++) {
            int kb8 = ks * 8;
            unsigned af[3][4];
            #pragma unroll
            for (int i = 0; i < 3; i++) {
                int mr = warpM * 48 + i * 16 + gid;
                af[i][0] = __float_as_uint(As[kb8 + tig    ][mr]);
                af[i][1] = __float_as_uint(As[kb8 + tig    ][mr + 8]);
                af[i][2] = __float_as_uint(As[kb8 + tig + 4][mr]);
                af[i][3] = __float_as_uint(As[kb8 + tig + 4][mr + 8]);
            }
            unsigned bf[3][2];
            #pragma unroll
            for (int j = 0; j < 3; j++) {
                int nc = warpN * 24 + j * 8 + gid;
                bf[j][0] = __float_as_uint(Bs[kb8 + tig    ][nc]);
                bf[j][1] = __float_as_uint(Bs[kb8 + tig + 4][nc]);
            }
            #pragma unroll
            for (int i = 0; i < 3; i++)
                #pragma unroll
                for (int j = 0; j < 3; j++) {
                    asm volatile(
                        "mma.sync.aligned.m16n8k8.row.col.f32.tf32.tf32.f32 "
                        "{%0,%1,%2,%3},{%4,%5,%6,%7},{%8,%9},{%0,%1,%2,%3};\n"
                        : "+f"(acc[i][j][0]), "+f"(acc[i][j][1]),
                          "+f"(acc[i][j][2]), "+f"(acc[i][j][3])
                        : "r"(af[i][0]), "r"(af[i][1]), "r"(af[i][2]), "r"(af[i][3]),
                          "r"(bf[j][0]), "r"(bf[j][1]));
                }
        }
        __syncthreads();
    }

    float* cb = g_ctxT + (size_t)bh * CH * CH;
    #pragma unroll
    for (int i = 0; i < 3; i++) {
        int e0 = warpM * 48 + i * 16 + gid;
        int e1 = e0 + 8;
        #pragma unroll
        for (int j = 0; j < 3; j++) {
            int d0 = warpN * 24 + j * 8 + 2 * tig;
            atomicAdd(&cb[e0 * CH + d0    ], acc[i][j][0]);
            atomicAdd(&cb[e0 * CH + d0 + 1], acc[i][j][1]);
            atomicAdd(&cb[e1 * CH + d0    ], acc[i][j][2]);
            atomicAdd(&cb[e1 * CH + d0 + 1], acc[i][j][3]);
        }
    }
}

// ---------------- final: LN(y)*outg + (x-mean)*rstd*preg ----------------
__global__ void final_kernel(const float* __restrict__ x, const float* __restrict__ preg,
                             const float* __restrict__ outg, float* __restrict__ out)
{
    size_t i = (size_t)blockIdx.x * blockDim.x + threadIdx.x;
    if (i >= (size_t)BATCH * DIMC * NPIX) return;
    int pix = (int)(i & 4095);
    int bc  = (int)(i >> 12);
    int c   = bc % DIMC;
    int b   = bc / DIMC;
    int bp  = b * NPIX + pix;
    float xn = (x[i]   - g_mean[bp])  * g_rstd[bp]  * preg[c];
    float yn = (g_y[i] - g_mean2[bp]) * g_rstd2[bp] * outg[c];
    out[i] = yn + xn;
}

// ---------------- launch ----------------
extern "C" void kernel_launch(void* const* d_in, const int* in_sizes, int n_in,
                              void* d_out, int out_size)
{
    const float* x    = (const float*)d_in[0];
    const float* preg = (const float*)d_in[1];
    const float* Wqkv = (const float*)d_in[2];
    const float* Wout = (const float*)d_in[3];
    const float* bout = (const float*)d_in[4];
    const float* outg = (const float*)d_in[5];
    float* out = (float*)d_out;
    (void)in_sizes; (void)n_in; (void)out_size;

    // 1. prep folded (fp16-rounded) weights
    prep_w_kernel<<<(QKVROWS * 32 + 255) / 256, 256>>>(Wqkv, preg);

    // 2. QKV GEMM (fp16 MMA, double-buffered) with FUSED prenorm stats + LN epilogue
    h16gemm_kernel<0, QKVROWS, DIMC><<<dim3(NPIX / BN, QKVROWS / BM, BATCH), 256>>>(nullptr, x, nullptr);

    // 3. softmaxes (in place, fp16)
    q_softmax_kernel<<<(BATCH * HEADS * NPIX) / 128, 128>>>();
    k_softmax_kernel<<<BATCH * DIMC, 256>>>();

    // 4. context (tf32 MMA over fp16 inputs) and apply to q (fp16 MMA)
    zero_ctx_kernel<<<(BATCH * HEADS * CH * CH + 255) / 256, 256>>>();
    ctx_tf32_kernel<<<dim3(CTX_SPLIT, BATCH * HEADS), 256>>>();
    h16gemm_kernel<2, CH, CH><<<dim3(NPIX / BN, 1, BATCH * HEADS), 256>>>(nullptr, nullptr, nullptr);

    // 5. out projection + bias (fp16 MMA, fp32 out)
    h16gemm_kernel<1, DIMC, DIMC><<<dim3(NPIX / BN, DIMC / BM, BATCH), 256>>>(Wout, nullptr, bout);

    // 6. out-LN stats + fused LN/residual epilogue
    chan_stats2_kernel<<<(BATCH * NPIX) / 256, 256>>>();
    final_kernel<<<(int)(((size_t)BATCH * DIMC * NPIX + 255) / 256), 256>>>(x, preg, outg, out);
}

// round 11
// speedup vs baseline: 1.1248x; 1.0593x over previous
#include <cuda_runtime.h>
#include <cuda_fp16.h>
#include <math.h>

// ---------------- problem constants ----------------
#define DIMC   384
#define NPIX   4096
#define BATCH  16
#define HEADS  4
#define CH     96
#define QKVROWS 1152
#define QSCALE 0.1020620726159658f   // 96^-0.5
#define CTX_SPLIT 8

// ---------------- scratch (device globals; allocation-free contract) ----------------
__device__ float  g_Wg[QKVROWS * DIMC];
__device__ float  g_wsum[QKVROWS];
__device__ float  g_mean[BATCH * NPIX];
__device__ float  g_rstd[BATCH * NPIX];
__device__ float  g_sumY[BATCH * NPIX];      // out-LN partial sums (atomics)
__device__ float  g_sum2Y[BATCH * NPIX];
__device__ __half g_qkvh[(size_t)BATCH * QKVROWS * NPIX];   // 151 MB, fp16
__device__ float  g_ctxT[BATCH * HEADS * CH * CH];          // ctx^T: [bh][e][d]
__device__ __half g_attnh[(size_t)BATCH * DIMC * NPIX];     // 50 MB, fp16
__device__ float  g_y[(size_t)BATCH * DIMC * NPIX];         // 100 MB

// ---------------- prep: W' = fp16-rounded(Wqkv * prenorm_g), row sums ----------------
__global__ void prep_w_kernel(const float* __restrict__ W, const float* __restrict__ g)
{
    int warp = (blockIdx.x * blockDim.x + threadIdx.x) >> 5;
    int lane = threadIdx.x & 31;
    if (warp >= QKVROWS) return;
    float s = 0.f;
    for (int c = lane; c < DIMC; c += 32) {
        float w = __half2float(__float2half_rn(W[warp * DIMC + c] * g[c]));
        g_Wg[warp * DIMC + c] = w;
        s += w;
    }
    #pragma unroll
    for (int o = 16; o > 0; o >>= 1) s += __shfl_down_sync(0xffffffffu, s, o);
    if (lane == 0) g_wsum[warp] = s;
}

// ---------------- zero: ctx accumulator + out-LN sum buffers ----------------
__global__ void zero_kernel()
{
    int i = blockIdx.x * blockDim.x + threadIdx.x;
    if (i < BATCH * HEADS * CH * CH) g_ctxT[i] = 0.f;
    if (i < BATCH * NPIX) { g_sumY[i] = 0.f; g_sum2Y[i] = 0.f; }
}

// ---------------- ldmatrix helper ----------------
__device__ __forceinline__ void ldsm_x4(unsigned &r0, unsigned &r1, unsigned &r2, unsigned &r3,
                                        unsigned addr)
{
    asm volatile("ldmatrix.sync.aligned.m8n8.x4.shared.b16 {%0,%1,%2,%3}, [%4];"
                 : "=r"(r0), "=r"(r1), "=r"(r2), "=r"(r3) : "r"(addr));
}

// =======================================================================
// fp16 tensor-core GEMM (fp32 accum): 128x128x16, 256 thr (8 warps 4x2),
// warp tile 32x64, mma.sync.m16n8k16, double-buffered smem, LDSM frags.
// KIND 0: qkv(h) = rstd*(Wg@x - mean*wsum)   + fused prenorm stats
// KIND 1: y(f32) = Wout@attn + bout          + fused out-LN partial sums
// KIND 2: attn(h)= ctxT@q (per b,h)
// =======================================================================
#define BM 128
#define BN 128
#define BK 16
#define PADH 8                       // k-stride = 24 halves = 48B (16B-aligned)
#define KSTR (BK + PADH)             // 24
#define STAGEB (128 * KSTR * 2)      // bytes per stage = 6144

template<int KIND, int M, int K>
__global__ __launch_bounds__(256, 2)
void h16gemm_kernel(const float* __restrict__ Aext, const float* __restrict__ Bext,
                    const float* __restrict__ bias)
{
    const int N = NPIX;
    constexpr bool HALF_B = (KIND != 0);
    __shared__ __half As[2][BM][KSTR];
    __shared__ __half Bs[2][BN][KSTR];
    __shared__ float  sred[256], sred2[256];
    __shared__ float  meanS[BN], rstdS[BN];

    int z = blockIdx.z;
    const float* A; const float* Bf = nullptr; const __half* Bh = nullptr;
    float* Cf = nullptr; __half* Ch = nullptr;

    if (KIND == 0) {
        A  = g_Wg;
        Bf = Bext + (size_t)z * K * N;
        Ch = g_qkvh + (size_t)z * M * N;
    } else if (KIND == 1) {
        A  = Aext;
        Bh = g_attnh + (size_t)z * K * N;
        Cf = g_y + (size_t)z * M * N;
    } else { // KIND == 2
        int b = z >> 2, h = z & 3;
        A  = g_ctxT + (size_t)z * CH * CH;
        Bh = g_qkvh + ((size_t)b * QKVROWS + h * CH) * N;   // q region
        Ch = g_attnh + ((size_t)b * DIMC + h * CH) * N;
    }

    int tid  = threadIdx.x;
    int lane = tid & 31;
    int wid  = tid >> 5;
    int warpM = wid & 3;
    int warpN = wid >> 2;
    int gid = lane >> 2;
    int tig = lane & 3;

    int rowBase = blockIdx.y * BM;
    int colBase = blockIdx.x * BN;

    // B-load coords
    int tn  = tid & 127;            // float-B path
    int kg  = tid >> 7;             // 0..1 -> 8 k rows each
    int tn2 = (tid & 63) << 1;      // half-B path: 2 columns
    int kg4 = tid >> 6;             // 0..3 -> 4 k rows each

    // LDSM addresses (stage-0 base; add STAGEB for stage 1)
    unsigned aBase = (unsigned)__cvta_generic_to_shared(&As[0][0][0]);
    unsigned bBase = (unsigned)__cvta_generic_to_shared(&Bs[0][0][0]);
    // A: lanes 0-15 -> rows m0..15 (k=0), lanes 16-31 -> same rows (k=8)
    unsigned aOff0 = ((unsigned)((warpM * 32 + (lane & 15)) * KSTR + (lane >> 4) * 8)) * 2;
    // B: tile pair jj -> rows n = warpN*64 + jj*16 + (lane>>4)*8 + (lane&7), k = ((lane>>3)&1)*8
    unsigned bRow  = (unsigned)(warpN * 64 + ((lane >> 4) * 8) + (lane & 7));
    unsigned bOffB = (bRow * KSTR + ((lane >> 3) & 1) * 8) * 2;

    float acc[2][8][4];
    #pragma unroll
    for (int i = 0; i < 2; i++)
        #pragma unroll
        for (int j = 0; j < 8; j++)
            #pragma unroll
            for (int t = 0; t < 4; t++) acc[i][j][t] = 0.f;

    float4  aReg[2];
    float   bReg[8];
    __half2 bRegH[4];
    float   statS = 0.f, statS2 = 0.f;

    const int NT = K / BK;

    // ---- stage + commit tile 0 ----
    #pragma unroll
    for (int i = 0; i < 2; i++) {
        int idx = tid + i * 256;
        int r   = idx >> 2;
        int c4  = (idx & 3) << 2;
        int gr  = rowBase + r;
        aReg[i] = (gr < M) ? *(const float4*)&A[(size_t)gr * K + c4]
                           : make_float4(0.f, 0.f, 0.f, 0.f);
    }
    if (HALF_B) {
        #pragma unroll
        for (int j = 0; j < 4; j++)
            bRegH[j] = *(const __half2*)&Bh[(size_t)(kg4 * 4 + j) * N + colBase + tn2];
    } else {
        #pragma unroll
        for (int j = 0; j < 8; j++)
            bReg[j] = Bf[(size_t)(kg * 8 + j) * N + colBase + tn];
    }
    #pragma unroll
    for (int i = 0; i < 2; i++) {
        int idx = tid + i * 256;
        int r   = idx >> 2;
        int c4  = (idx & 3) << 2;
        *(half2*)&As[0][r][c4]     = __floats2half2_rn(aReg[i].x, aReg[i].y);
        *(half2*)&As[0][r][c4 + 2] = __floats2half2_rn(aReg[i].z, aReg[i].w);
    }
    if (HALF_B) {
        #pragma unroll
        for (int j = 0; j < 4; j++) {
            Bs[0][tn2    ][kg4 * 4 + j] = __low2half(bRegH[j]);
            Bs[0][tn2 + 1][kg4 * 4 + j] = __high2half(bRegH[j]);
        }
    } else {
        #pragma unroll
        for (int j = 0; j < 4; j++)
            *(half2*)&Bs[0][tn][kg * 8 + 2 * j] = __floats2half2_rn(bReg[2 * j], bReg[2 * j + 1]);
        if (KIND == 0) {
            #pragma unroll
            for (int j = 0; j < 8; j++) { statS += bReg[j]; statS2 += bReg[j] * bReg[j]; }
        }
    }
    __syncthreads();

    // ---- mainloop: 1 sync/iter, LDSM fragments ----
    for (int kt = 0; kt < NT; kt++) {
        int cur = kt & 1;
        bool hasNext = (kt + 1 < NT);

        if (hasNext) {
            int k1 = (kt + 1) * BK;
            #pragma unroll
            for (int i = 0; i < 2; i++) {
                int idx = tid + i * 256;
                int r   = idx >> 2;
                int c4  = (idx & 3) << 2;
                int gr  = rowBase + r;
                aReg[i] = (gr < M) ? *(const float4*)&A[(size_t)gr * K + k1 + c4]
                                   : make_float4(0.f, 0.f, 0.f, 0.f);
            }
            if (HALF_B) {
                #pragma unroll
                for (int j = 0; j < 4; j++)
                    bRegH[j] = *(const __half2*)&Bh[(size_t)(k1 + kg4 * 4 + j) * N + colBase + tn2];
            } else {
                #pragma unroll
                for (int j = 0; j < 8; j++)
                    bReg[j] = Bf[(size_t)(k1 + kg * 8 + j) * N + colBase + tn];
            }
        }

        // fragments via ldmatrix
        unsigned stOff = cur ? (unsigned)STAGEB : 0u;
        unsigned af[2][4];
        #pragma unroll
        for (int i = 0; i < 2; i++)
            ldsm_x4(af[i][0], af[i][1], af[i][2], af[i][3],
                    aBase + stOff + aOff0 + (unsigned)(i * 16 * KSTR * 2));
        unsigned bf[8][2];
        #pragma unroll
        for (int jj = 0; jj < 4; jj++) {
            unsigned r0, r1, r2, r3;
            ldsm_x4(r0, r1, r2, r3,
                    bBase + stOff + bOffB + (unsigned)(jj * 16 * KSTR * 2));
            bf[2 * jj][0]     = r0; bf[2 * jj][1]     = r1;
            bf[2 * jj + 1][0] = r2; bf[2 * jj + 1][1] = r3;
        }

        #pragma unroll
        for (int i = 0; i < 2; i++)
            #pragma unroll
            for (int j = 0; j < 8; j++) {
                asm volatile(
                    "mma.sync.aligned.m16n8k16.row.col.f32.f16.f16.f32 "
                    "{%0,%1,%2,%3},{%4,%5,%6,%7},{%8,%9},{%0,%1,%2,%3};\n"
                    : "+f"(acc[i][j][0]), "+f"(acc[i][j][1]),
                      "+f"(acc[i][j][2]), "+f"(acc[i][j][3])
                    : "r"(af[i][0]), "r"(af[i][1]), "r"(af[i][2]), "r"(af[i][3]),
                      "r"(bf[j][0]), "r"(bf[j][1]));
            }

        if (hasNext) {
            int nxt = cur ^ 1;
            #pragma unroll
            for (int i = 0; i < 2; i++) {
                int idx = tid + i * 256;
                int r   = idx >> 2;
                int c4  = (idx & 3) << 2;
                *(half2*)&As[nxt][r][c4]     = __floats2half2_rn(aReg[i].x, aReg[i].y);
                *(half2*)&As[nxt][r][c4 + 2] = __floats2half2_rn(aReg[i].z, aReg[i].w);
            }
            if (HALF_B) {
                #pragma unroll
                for (int j = 0; j < 4; j++) {
                    Bs[nxt][tn2    ][kg4 * 4 + j] = __low2half(bRegH[j]);
                    Bs[nxt][tn2 + 1][kg4 * 4 + j] = __high2half(bRegH[j]);
                }
            } else {
                #pragma unroll
                for (int j = 0; j < 4; j++)
                    *(half2*)&Bs[nxt][tn][kg * 8 + 2 * j] =
                        __floats2half2_rn(bReg[2 * j], bReg[2 * j + 1]);
                if (KIND == 0) {
                    #pragma unroll
                    for (int j = 0; j < 8; j++) { statS += bReg[j]; statS2 += bReg[j] * bReg[j]; }
                }
            }
        }
        __syncthreads();
    }

    // ---- KIND 0: block-local prenorm LN stats ----
    if (KIND == 0) {
        sred[tid] = statS; sred2[tid] = statS2;
        __syncthreads();
        if (tid < 128) {
            float st  = sred[tid]  + sred[tid + 128];
            float s2t = sred2[tid] + sred2[tid + 128];
            float m   = st * (1.f / DIMC);
            float var = s2t * (1.f / DIMC) - m * m;
            float r   = rsqrtf(var + 1e-5f);
            meanS[tid] = m; rstdS[tid] = r;
            if (blockIdx.y == 0) {
                g_mean[(size_t)z * NPIX + colBase + tid] = m;
                g_rstd[(size_t)z * NPIX + colBase + tid] = r;
            }
        }
        __syncthreads();
    }
    // ---- KIND 1: init per-column stat accumulators ----
    if (KIND == 1) {
        sred[tid] = 0.f; sred2[tid] = 0.f;
        __syncthreads();
    }

    float colS[16], colS2[16];
    if (KIND == 1) {
        #pragma unroll
        for (int t = 0; t < 16; t++) { colS[t] = 0.f; colS2[t] = 0.f; }
    }

    // ---------------- epilogue ----------------
    #pragma unroll
    for (int i = 0; i < 2; i++) {
        int r0 = rowBase + warpM * 32 + i * 16 + gid;
        int r1 = r0 + 8;
        float w0 = 0.f, w1 = 0.f, bb0 = 0.f, bb1 = 0.f;
        if (KIND == 0)      { w0 = g_wsum[r0]; w1 = g_wsum[r1]; }
        else if (KIND == 1) { bb0 = bias[r0];  bb1 = bias[r1]; }
        #pragma unroll
        for (int j = 0; j < 8; j++) {
            int cc = warpN * 64 + j * 8 + 2 * tig;
            int c0 = colBase + cc;
            if (KIND == 0) {
                float m0 = meanS[cc], m1 = meanS[cc + 1];
                float v0 = rstdS[cc], v1 = rstdS[cc + 1];
                *(half2*)&Ch[(size_t)r0 * N + c0] =
                    __floats2half2_rn(v0 * (acc[i][j][0] - m0 * w0),
                                      v1 * (acc[i][j][1] - m1 * w0));
                *(half2*)&Ch[(size_t)r1 * N + c0] =
                    __floats2half2_rn(v0 * (acc[i][j][2] - m0 * w1),
                                      v1 * (acc[i][j][3] - m1 * w1));
            } else if (KIND == 1) {
                float y00 = acc[i][j][0] + bb0, y01 = acc[i][j][1] + bb0;
                float y10 = acc[i][j][2] + bb1, y11 = acc[i][j][3] + bb1;
                *(float2*)&Cf[(size_t)r0 * N + c0] = make_float2(y00, y01);
                *(float2*)&Cf[(size_t)r1 * N + c0] = make_float2(y10, y11);
                colS [2 * j]     += y00 + y10;
                colS [2 * j + 1] += y01 + y11;
                colS2[2 * j]     += y00 * y00 + y10 * y10;
                colS2[2 * j + 1] += y01 * y01 + y11 * y11;
            } else {
                if (r0 < M)
                    *(half2*)&Ch[(size_t)r0 * N + c0] =
                        __floats2half2_rn(acc[i][j][0], acc[i][j][1]);
                if (r1 < M)
                    *(half2*)&Ch[(size_t)r1 * N + c0] =
                        __floats2half2_rn(acc[i][j][2], acc[i][j][3]);
            }
        }
    }

    // ---- KIND 1: reduce per-column sums -> global atomics ----
    if (KIND == 1) {
        #pragma unroll
        for (int t = 0; t < 8; t++) {
            int cc = warpN * 64 + t * 8 + 2 * tig;
            atomicAdd(&sred[cc],      colS[2 * t]);
            atomicAdd(&sred[cc + 1],  colS[2 * t + 1]);
            atomicAdd(&sred2[cc],     colS2[2 * t]);
            atomicAdd(&sred2[cc + 1], colS2[2 * t + 1]);
        }
        __syncthreads();
        if (tid < 128) {
            atomicAdd(&g_sumY [(size_t)z * NPIX + colBase + tid], sred[tid]);
            atomicAdd(&g_sum2Y[(size_t)z * NPIX + colBase + tid], sred2[tid]);
        }
    }
}

// ---------------- q softmax over channel dim (96) per (b,h,pixel), fp16 io ----------------
__global__ __launch_bounds__(128) void q_softmax_kernel()
{
    int idx = blockIdx.x * blockDim.x + threadIdx.x;
    if (idx >= BATCH * HEADS * NPIX) return;
    int pix = idx & 4095;
    int h   = (idx >> 12) & 3;
    int b   = idx >> 14;
    __half* base = g_qkvh + ((size_t)b * QKVROWS + h * CH) * NPIX + pix;

    float v[CH];
    float mx = -1e30f;
    #pragma unroll
    for (int d = 0; d < CH; d++) {
        v[d] = __half2float(base[(size_t)d * NPIX]);
        mx = fmaxf(mx, v[d]);
    }
    float s = 0.f;
    #pragma unroll
    for (int d = 0; d < CH; d++) {
        v[d] = __expf(v[d] - mx);
        s += v[d];
    }
    float inv = QSCALE / s;
    #pragma unroll
    for (int d = 0; d < CH; d++) base[(size_t)d * NPIX] = __float2half_rn(v[d] * inv);
}

// ---------------- k softmax over spatial dim (4096) per (b, channel), fp16 io ----------------
__global__ __launch_bounds__(256) void k_softmax_kernel()
{
    int row = blockIdx.x;
    int b = row / DIMC, r = row % DIMC;
    __half* base = g_qkvh + ((size_t)b * QKVROWS + DIMC + r) * NPIX;
    int tid  = threadIdx.x;
    int lane = tid & 31, warp = tid >> 5;

    float f[16];
    float mx = -1e30f;
    #pragma unroll
    for (int j = 0; j < 2; j++) {
        uint4 u = *(const uint4*)&base[(size_t)(j * 256 + tid) * 8];
        const __half2* hp = (const __half2*)&u;
        #pragma unroll
        for (int t = 0; t < 4; t++) {
            float2 p = __half22float2(hp[t]);
            f[j * 8 + 2 * t]     = p.x;
            f[j * 8 + 2 * t + 1] = p.y;
            mx = fmaxf(mx, fmaxf(p.x, p.y));
        }
    }
    __shared__ float smax[8];
    __shared__ float ssum[8];
    #pragma unroll
    for (int o = 16; o > 0; o >>= 1) mx = fmaxf(mx, __shfl_xor_sync(0xffffffffu, mx, o));
    if (lane == 0) smax[warp] = mx;
    __syncthreads();
    mx = smax[0];
    #pragma unroll
    for (int w = 1; w < 8; w++) mx = fmaxf(mx, smax[w]);

    float s = 0.f;
    #pragma unroll
    for (int t = 0; t < 16; t++) {
        f[t] = __expf(f[t] - mx);
        s += f[t];
    }
    #pragma unroll
    for (int o = 16; o > 0; o >>= 1) s += __shfl_xor_sync(0xffffffffu, s, o);
    if (lane == 0) ssum[warp] = s;
    __syncthreads();
    s = 0.f;
    #pragma unroll
    for (int w = 0; w < 8; w++) s += ssum[w];

    float inv = 1.f / s;
    #pragma unroll
    for (int j = 0; j < 2; j++) {
        uint4 u;
        __half2* hp = (__half2*)&u;
        #pragma unroll
        for (int t = 0; t < 4; t++)
            hp[t] = __floats2half2_rn(f[j * 8 + 2 * t] * inv, f[j * 8 + 2 * t + 1] * inv);
        *(uint4*)&base[(size_t)(j * 256 + tid) * 8] = u;
    }
}

// =======================================================================
// ctx via tf32 MMA: ctxT[e][d] = sum_n v[e,n]*k[d,n], fp16 inputs
// =======================================================================
#define BKC 16
__global__ __launch_bounds__(256)
void ctx_tf32_kernel()
{
    int sk = blockIdx.x;
    int bh = blockIdx.y;
    int b = bh >> 2, h = bh & 3;
    const __half* kb = g_qkvh + ((size_t)b * QKVROWS + DIMC     + h * CH) * NPIX;
    const __half* vb = g_qkvh + ((size_t)b * QKVROWS + 2 * DIMC + h * CH) * NPIX;

    __shared__ float As[BKC][CH + 4];
    __shared__ float Bs[BKC][CH + 4];

    int tid  = threadIdx.x;
    int lane = tid & 31;
    int wid  = tid >> 5;
    int warpM = wid & 1;
    int warpN = wid >> 1;
    int gid = lane >> 2;
    int tig = lane & 3;

    float acc[3][3][4];
    #pragma unroll
    for (int i = 0; i < 3; i++)
        #pragma unroll
        for (int j = 0; j < 3; j++)
            #pragma unroll
            for (int t = 0; t < 4; t++) acc[i][j][t] = 0.f;

    const int KLEN = NPIX / CTX_SPLIT;
    int n0 = sk * KLEN;

    for (int nt = 0; nt < KLEN; nt += BKC) {
        #pragma unroll
        for (int i = 0; i < 2; i++) {
            int idx = tid + i * 256;
            if (idx < 384) {
                int r  = idx >> 2;
                int c4 = (idx & 3) << 2;
                const __half2* pv = (const __half2*)&vb[(size_t)r * NPIX + n0 + nt + c4];
                float2 v0 = __half22float2(pv[0]);
                float2 v1 = __half22float2(pv[1]);
                As[c4 + 0][r] = v0.x; As[c4 + 1][r] = v0.y;
                As[c4 + 2][r] = v1.x; As[c4 + 3][r] = v1.y;
                const __half2* pk = (const __half2*)&kb[(size_t)r * NPIX + n0 + nt + c4];
                float2 k0 = __half22float2(pk[0]);
                float2 k1 = __half22float2(pk[1]);
                Bs[c4 + 0][r] = k0.x; Bs[c4 + 1][r] = k0.y;
                Bs[c4 + 2][r] = k1.x; Bs[c4 + 3][r] = k1.y;
            }
        }
        __syncthreads();

        #pragma unroll
        for (int ks = 0; ks < 2; ks++) {
            int kb8 = ks * 8;
            unsigned af[3][4];
            #pragma unroll
            for (int i = 0; i < 3; i++) {
                int mr = warpM * 48 + i * 16 + gid;
                af[i][0] = __float_as_uint(As[kb8 + tig    ][mr]);
                af[i][1] = __float_as_uint(As[kb8 + tig    ][mr + 8]);
                af[i][2] = __float_as_uint(As[kb8 + tig + 4][mr]);
                af[i][3] = __float_as_uint(As[kb8 + tig + 4][mr + 8]);
            }
            unsigned bf[3][2];
            #pragma unroll
            for (int j = 0; j < 3; j++) {
                int nc = warpN * 24 + j * 8 + gid;
                bf[j][0] = __float_as_uint(Bs[kb8 + tig    ][nc]);
                bf[j][1] = __float_as_uint(Bs[kb8 + tig + 4][nc]);
            }
            #pragma unroll
            for (int i = 0; i < 3; i++)
                #pragma unroll
                for (int j = 0; j < 3; j++) {
                    asm volatile(
                        "mma.sync.aligned.m16n8k8.row.col.f32.tf32.tf32.f32 "
                        "{%0,%1,%2,%3},{%4,%5,%6,%7},{%8,%9},{%0,%1,%2,%3};\n"
                        : "+f"(acc[i][j][0]), "+f"(acc[i][j][1]),
                          "+f"(acc[i][j][2]), "+f"(acc[i][j][3])
                        : "r"(af[i][0]), "r"(af[i][1]), "r"(af[i][2]), "r"(af[i][3]),
                          "r"(bf[j][0]), "r"(bf[j][1]));
                }
        }
        __syncthreads();
    }

    float* cb = g_ctxT + (size_t)bh * CH * CH;
    #pragma unroll
    for (int i = 0; i < 3; i++) {
        int e0 = warpM * 48 + i * 16 + gid;
        int e1 = e0 + 8;
        #pragma unroll
        for (int j = 0; j < 3; j++) {
            int d0 = warpN * 24 + j * 8 + 2 * tig;
            atomicAdd(&cb[e0 * CH + d0    ], acc[i][j][0]);
            atomicAdd(&cb[e0 * CH + d0 + 1], acc[i][j][1]);
            atomicAdd(&cb[e1 * CH + d0    ], acc[i][j][2]);
            atomicAdd(&cb[e1 * CH + d0 + 1], acc[i][j][3]);
        }
    }
}

// ---------------- final: LN(y from sums)*outg + (x-mean)*rstd*preg ----------------
__global__ void final_kernel(const float* __restrict__ x, const float* __restrict__ preg,
                             const float* __restrict__ outg, float* __restrict__ out)
{
    size_t i = (size_t)blockIdx.x * blockDim.x + threadIdx.x;
    if (i >= (size_t)BATCH * DIMC * NPIX) return;
    int pix = (int)(i & 4095);
    int bc  = (int)(i >> 12);
    int c   = bc % DIMC;
    int b   = bc / DIMC;
    int bp  = b * NPIX + pix;
    float m2  = g_sumY[bp] * (1.f / DIMC);
    float var = g_sum2Y[bp] * (1.f / DIMC) - m2 * m2;
    float r2  = rsqrtf(var + 1e-5f);
    float xn = (x[i]   - g_mean[bp]) * g_rstd[bp] * preg[c];
    float yn = (g_y[i] - m2)         * r2         * outg[c];
    out[i] = yn + xn;
}

// ---------------- launch ----------------
extern "C" void kernel_launch(void* const* d_in, const int* in_sizes, int n_in,
                              void* d_out, int out_size)
{
    const float* x    = (const float*)d_in[0];
    const float* preg = (const float*)d_in[1];
    const float* Wqkv = (const float*)d_in[2];
    const float* Wout = (const float*)d_in[3];
    const float* bout = (const float*)d_in[4];
    const float* outg = (const float*)d_in[5];
    float* out = (float*)d_out;
    (void)in_sizes; (void)n_in; (void)out_size;

    // 1. prep folded weights + zero accumulators
    prep_w_kernel<<<(QKVROWS * 32 + 255) / 256, 256>>>(Wqkv, preg);
    zero_kernel<<<(BATCH * HEADS * CH * CH + 255) / 256, 256>>>();

    // 2. QKV GEMM (fp16 MMA, LDSM frags) with fused prenorm stats + LN epilogue
    h16gemm_kernel<0, QKVROWS, DIMC><<<dim3(NPIX / BN, QKVROWS / BM, BATCH), 256>>>(nullptr, x, nullptr);

    // 3. softmaxes (in place, fp16)
    q_softmax_kernel<<<(BATCH * HEADS * NPIX) / 128, 128>>>();
    k_softmax_kernel<<<BATCH * DIMC, 256>>>();

    // 4. context + apply
    ctx_tf32_kernel<<<dim3(CTX_SPLIT, BATCH * HEADS), 256>>>();
    h16gemm_kernel<2, CH, CH><<<dim3(NPIX / BN, 1, BATCH * HEADS), 256>>>(nullptr, nullptr, nullptr);

    // 5. out projection + bias with fused out-LN partial sums
    h16gemm_kernel<1, DIMC, DIMC><<<dim3(NPIX / BN, DIMC / BM, BATCH), 256>>>(Wout, nullptr, bout);

    // 6. fused LN/residual epilogue (stats from sums)
    final_kernel<<<(int)(((size_t)BATCH * DIMC * NPIX + 255) / 256), 256>>>(x, preg, outg, out);
}

// round 12
// speedup vs baseline: 1.1445x; 1.0175x over previous
#include <cuda_runtime.h>
#include <cuda_fp16.h>
#include <math.h>

// ---------------- problem constants ----------------
#define DIMC   384
#define NPIX   4096
#define BATCH  16
#define HEADS  4
#define CH     96
#define QKVROWS 1152
#define QSCALE 0.1020620726159658f   // 96^-0.5
#define CTX_SPLIT 8

// ---------------- scratch (device globals; allocation-free contract) ----------------
__device__ float  g_Wg[QKVROWS * DIMC];
__device__ float  g_wsum[QKVROWS];
__device__ float  g_mean[BATCH * NPIX];
__device__ float  g_rstd[BATCH * NPIX];
__device__ float  g_sumY[BATCH * NPIX];      // out-LN partial sums (atomics)
__device__ float  g_sum2Y[BATCH * NPIX];
__device__ __half g_qkvh[(size_t)BATCH * QKVROWS * NPIX];   // 151 MB, fp16
__device__ float  g_ctxT[BATCH * HEADS * CH * CH];          // ctx^T: [bh][e][d]
__device__ float  g_Wfold[(size_t)BATCH * DIMC * DIMC];     // folded Wout@ctxT, 9.4 MB
__device__ __half g_yh[(size_t)BATCH * DIMC * NPIX];        // 50 MB, fp16

// ---------------- prep: W' = fp16-rounded(Wqkv * prenorm_g), row sums ----------------
__global__ void prep_w_kernel(const float* __restrict__ W, const float* __restrict__ g)
{
    int warp = (blockIdx.x * blockDim.x + threadIdx.x) >> 5;
    int lane = threadIdx.x & 31;
    if (warp >= QKVROWS) return;
    float s = 0.f;
    for (int c = lane; c < DIMC; c += 32) {
        float w = __half2float(__float2half_rn(W[warp * DIMC + c] * g[c]));
        g_Wg[warp * DIMC + c] = w;
        s += w;
    }
    #pragma unroll
    for (int o = 16; o > 0; o >>= 1) s += __shfl_down_sync(0xffffffffu, s, o);
    if (lane == 0) g_wsum[warp] = s;
}

// ---------------- zero: ctx accumulator + out-LN sum buffers ----------------
__global__ void zero_kernel()
{
    int i = blockIdx.x * blockDim.x + threadIdx.x;
    if (i < BATCH * HEADS * CH * CH) g_ctxT[i] = 0.f;
    if (i < BATCH * NPIX) { g_sumY[i] = 0.f; g_sum2Y[i] = 0.f; }
}

// ---------------- ldmatrix helper ----------------
__device__ __forceinline__ void ldsm_x4(unsigned &r0, unsigned &r1, unsigned &r2, unsigned &r3,
                                        unsigned addr)
{
    asm volatile("ldmatrix.sync.aligned.m8n8.x4.shared.b16 {%0,%1,%2,%3}, [%4];"
                 : "=r"(r0), "=r"(r1), "=r"(r2), "=r"(r3) : "r"(addr));
}

// =======================================================================
// fp16 tensor-core GEMM (fp32 accum): 128x128x16, 256 thr (8 warps 4x2),
// warp tile 32x64, mma.sync.m16n8k16, double-buffered smem, LDSM frags.
// KIND 0: qkv(h) = rstd*(Wg@x - mean*wsum)   + fused prenorm stats
// KIND 1: y(h)   = Wfold_b@q + bout          + fused out-LN partial sums
// =======================================================================
#define BM 128
#define BN 128
#define BK 16
#define PADH 8                       // k-stride = 24 halves = 48B (16B-aligned)
#define KSTR (BK + PADH)             // 24
#define STAGEB (128 * KSTR * 2)      // bytes per stage = 6144

template<int KIND, int M, int K>
__global__ __launch_bounds__(256, 2)
void h16gemm_kernel(const float* __restrict__ Bext, const float* __restrict__ bias)
{
    const int N = NPIX;
    constexpr bool HALF_B = (KIND != 0);
    __shared__ __half As[2][BM][KSTR];
    __shared__ __half Bs[2][BN][KSTR];
    __shared__ float  sred[256], sred2[256];
    __shared__ float  meanS[BN], rstdS[BN];

    int z = blockIdx.z;
    const float* A; const float* Bf = nullptr; const __half* Bh = nullptr;
    __half* Ch;

    if (KIND == 0) {
        A  = g_Wg;
        Bf = Bext + (size_t)z * K * N;
        Ch = g_qkvh + (size_t)z * M * N;
    } else {
        A  = g_Wfold + (size_t)z * DIMC * DIMC;
        Bh = g_qkvh + (size_t)z * QKVROWS * N;   // q region (rows 0..383)
        Ch = g_yh + (size_t)z * M * N;
    }

    int tid  = threadIdx.x;
    int lane = tid & 31;
    int wid  = tid >> 5;
    int warpM = wid & 3;
    int warpN = wid >> 2;
    int gid = lane >> 2;
    int tig = lane & 3;

    int rowBase = blockIdx.y * BM;
    int colBase = blockIdx.x * BN;

    // B-load coords
    int tn  = tid & 127;            // float-B path
    int kg  = tid >> 7;             // 0..1 -> 8 k rows each
    int tn2 = (tid & 63) << 1;      // half-B path: 2 columns
    int kg4 = tid >> 6;             // 0..3 -> 4 k rows each

    // LDSM addresses (stage-0 base; add STAGEB for stage 1)
    unsigned aBase = (unsigned)__cvta_generic_to_shared(&As[0][0][0]);
    unsigned bBase = (unsigned)__cvta_generic_to_shared(&Bs[0][0][0]);
    unsigned aOff0 = ((unsigned)((warpM * 32 + (lane & 15)) * KSTR + (lane >> 4) * 8)) * 2;
    unsigned bRow  = (unsigned)(warpN * 64 + ((lane >> 4) * 8) + (lane & 7));
    unsigned bOffB = (bRow * KSTR + ((lane >> 3) & 1) * 8) * 2;

    float acc[2][8][4];
    #pragma unroll
    for (int i = 0; i < 2; i++)
        #pragma unroll
        for (int j = 0; j < 8; j++)
            #pragma unroll
            for (int t = 0; t < 4; t++) acc[i][j][t] = 0.f;

    float4  aReg[2];
    float   bReg[8];
    __half2 bRegH[4];
    float   statS = 0.f, statS2 = 0.f;

    const int NT = K / BK;

    // ---- stage + commit tile 0 ----
    #pragma unroll
    for (int i = 0; i < 2; i++) {
        int idx = tid + i * 256;
        int r   = idx >> 2;
        int c4  = (idx & 3) << 2;
        int gr  = rowBase + r;
        aReg[i] = (gr < M) ? *(const float4*)&A[(size_t)gr * K + c4]
                           : make_float4(0.f, 0.f, 0.f, 0.f);
    }
    if (HALF_B) {
        #pragma unroll
        for (int j = 0; j < 4; j++)
            bRegH[j] = *(const __half2*)&Bh[(size_t)(kg4 * 4 + j) * N + colBase + tn2];
    } else {
        #pragma unroll
        for (int j = 0; j < 8; j++)
            bReg[j] = Bf[(size_t)(kg * 8 + j) * N + colBase + tn];
    }
    #pragma unroll
    for (int i = 0; i < 2; i++) {
        int idx = tid + i * 256;
        int r   = idx >> 2;
        int c4  = (idx & 3) << 2;
        *(half2*)&As[0][r][c4]     = __floats2half2_rn(aReg[i].x, aReg[i].y);
        *(half2*)&As[0][r][c4 + 2] = __floats2half2_rn(aReg[i].z, aReg[i].w);
    }
    if (HALF_B) {
        #pragma unroll
        for (int j = 0; j < 4; j++) {
            Bs[0][tn2    ][kg4 * 4 + j] = __low2half(bRegH[j]);
            Bs[0][tn2 + 1][kg4 * 4 + j] = __high2half(bRegH[j]);
        }
    } else {
        #pragma unroll
        for (int j = 0; j < 4; j++)
            *(half2*)&Bs[0][tn][kg * 8 + 2 * j] = __floats2half2_rn(bReg[2 * j], bReg[2 * j + 1]);
        if (KIND == 0) {
            #pragma unroll
            for (int j = 0; j < 8; j++) { statS += bReg[j]; statS2 += bReg[j] * bReg[j]; }
        }
    }
    __syncthreads();

    // ---- mainloop: 1 sync/iter, LDSM fragments ----
    for (int kt = 0; kt < NT; kt++) {
        int cur = kt & 1;
        bool hasNext = (kt + 1 < NT);

        if (hasNext) {
            int k1 = (kt + 1) * BK;
            #pragma unroll
            for (int i = 0; i < 2; i++) {
                int idx = tid + i * 256;
                int r   = idx >> 2;
                int c4  = (idx & 3) << 2;
                int gr  = rowBase + r;
                aReg[i] = (gr < M) ? *(const float4*)&A[(size_t)gr * K + k1 + c4]
                                   : make_float4(0.f, 0.f, 0.f, 0.f);
            }
            if (HALF_B) {
                #pragma unroll
                for (int j = 0; j < 4; j++)
                    bRegH[j] = *(const __half2*)&Bh[(size_t)(k1 + kg4 * 4 + j) * N + colBase + tn2];
            } else {
                #pragma unroll
                for (int j = 0; j < 8; j++)
                    bReg[j] = Bf[(size_t)(k1 + kg * 8 + j) * N + colBase + tn];
            }
        }

        unsigned stOff = cur ? (unsigned)STAGEB : 0u;
        unsigned af[2][4];
        #pragma unroll
        for (int i = 0; i < 2; i++)
            ldsm_x4(af[i][0], af[i][1], af[i][2], af[i][3],
                    aBase + stOff + aOff0 + (unsigned)(i * 16 * KSTR * 2));
        unsigned bf[8][2];
        #pragma unroll
        for (int jj = 0; jj < 4; jj++) {
            unsigned r0, r1, r2, r3;
            ldsm_x4(r0, r1, r2, r3,
                    bBase + stOff + bOffB + (unsigned)(jj * 16 * KSTR * 2));
            bf[2 * jj][0]     = r0; bf[2 * jj][1]     = r1;
            bf[2 * jj + 1][0] = r2; bf[2 * jj + 1][1] = r3;
        }

        #pragma unroll
        for (int i = 0; i < 2; i++)
            #pragma unroll
            for (int j = 0; j < 8; j++) {
                asm volatile(
                    "mma.sync.aligned.m16n8k16.row.col.f32.f16.f16.f32 "
                    "{%0,%1,%2,%3},{%4,%5,%6,%7},{%8,%9},{%0,%1,%2,%3};\n"
                    : "+f"(acc[i][j][0]), "+f"(acc[i][j][1]),
                      "+f"(acc[i][j][2]), "+f"(acc[i][j][3])
                    : "r"(af[i][0]), "r"(af[i][1]), "r"(af[i][2]), "r"(af[i][3]),
                      "r"(bf[j][0]), "r"(bf[j][1]));
            }

        if (hasNext) {
            int nxt = cur ^ 1;
            #pragma unroll
            for (int i = 0; i < 2; i++) {
                int idx = tid + i * 256;
                int r   = idx >> 2;
                int c4  = (idx & 3) << 2;
                *(half2*)&As[nxt][r][c4]     = __floats2half2_rn(aReg[i].x, aReg[i].y);
                *(half2*)&As[nxt][r][c4 + 2] = __floats2half2_rn(aReg[i].z, aReg[i].w);
            }
            if (HALF_B) {
                #pragma unroll
                for (int j = 0; j < 4; j++) {
                    Bs[nxt][tn2    ][kg4 * 4 + j] = __low2half(bRegH[j]);
                    Bs[nxt][tn2 + 1][kg4 * 4 + j] = __high2half(bRegH[j]);
                }
            } else {
                #pragma unroll
                for (int j = 0; j < 4; j++)
                    *(half2*)&Bs[nxt][tn][kg * 8 + 2 * j] =
                        __floats2half2_rn(bReg[2 * j], bReg[2 * j + 1]);
                if (KIND == 0) {
                    #pragma unroll
                    for (int j = 0; j < 8; j++) { statS += bReg[j]; statS2 += bReg[j] * bReg[j]; }
                }
            }
        }
        __syncthreads();
    }

    // ---- KIND 0: block-local prenorm LN stats ----
    if (KIND == 0) {
        sred[tid] = statS; sred2[tid] = statS2;
        __syncthreads();
        if (tid < 128) {
            float st  = sred[tid]  + sred[tid + 128];
            float s2t = sred2[tid] + sred2[tid + 128];
            float m   = st * (1.f / DIMC);
            float var = s2t * (1.f / DIMC) - m * m;
            float r   = rsqrtf(var + 1e-5f);
            meanS[tid] = m; rstdS[tid] = r;
            if (blockIdx.y == 0) {
                g_mean[(size_t)z * NPIX + colBase + tid] = m;
                g_rstd[(size_t)z * NPIX + colBase + tid] = r;
            }
        }
        __syncthreads();
    }
    if (KIND == 1) {
        sred[tid] = 0.f; sred2[tid] = 0.f;
        __syncthreads();
    }

    float colS[16], colS2[16];
    if (KIND == 1) {
        #pragma unroll
        for (int t = 0; t < 16; t++) { colS[t] = 0.f; colS2[t] = 0.f; }
    }

    // ---------------- epilogue ----------------
    #pragma unroll
    for (int i = 0; i < 2; i++) {
        int r0 = rowBase + warpM * 32 + i * 16 + gid;
        int r1 = r0 + 8;
        float w0 = 0.f, w1 = 0.f, bb0 = 0.f, bb1 = 0.f;
        if (KIND == 0)      { w0 = g_wsum[r0]; w1 = g_wsum[r1]; }
        else                { bb0 = bias[r0];  bb1 = bias[r1]; }
        #pragma unroll
        for (int j = 0; j < 8; j++) {
            int cc = warpN * 64 + j * 8 + 2 * tig;
            int c0 = colBase + cc;
            if (KIND == 0) {
                float m0 = meanS[cc], m1 = meanS[cc + 1];
                float v0 = rstdS[cc], v1 = rstdS[cc + 1];
                *(half2*)&Ch[(size_t)r0 * N + c0] =
                    __floats2half2_rn(v0 * (acc[i][j][0] - m0 * w0),
                                      v1 * (acc[i][j][1] - m1 * w0));
                *(half2*)&Ch[(size_t)r1 * N + c0] =
                    __floats2half2_rn(v0 * (acc[i][j][2] - m0 * w1),
                                      v1 * (acc[i][j][3] - m1 * w1));
            } else {
                // round to half FIRST; accumulate stats from the rounded values
                half2 h0 = __floats2half2_rn(acc[i][j][0] + bb0, acc[i][j][1] + bb0);
                half2 h1 = __floats2half2_rn(acc[i][j][2] + bb1, acc[i][j][3] + bb1);
                *(half2*)&Ch[(size_t)r0 * N + c0] = h0;
                *(half2*)&Ch[(size_t)r1 * N + c0] = h1;
                float2 f0 = __half22float2(h0);
                float2 f1 = __half22float2(h1);
                colS [2 * j]     += f0.x + f1.x;
                colS [2 * j + 1] += f0.y + f1.y;
                colS2[2 * j]     += f0.x * f0.x + f1.x * f1.x;
                colS2[2 * j + 1] += f0.y * f0.y + f1.y * f1.y;
            }
        }
    }

    // ---- KIND 1: reduce per-column sums -> global atomics ----
    if (KIND == 1) {
        #pragma unroll
        for (int t = 0; t < 8; t++) {
            int cc = warpN * 64 + t * 8 + 2 * tig;
            atomicAdd(&sred[cc],      colS[2 * t]);
            atomicAdd(&sred[cc + 1],  colS[2 * t + 1]);
            atomicAdd(&sred2[cc],     colS2[2 * t]);
            atomicAdd(&sred2[cc + 1], colS2[2 * t + 1]);
        }
        __syncthreads();
        if (tid < 128) {
            atomicAdd(&g_sumY [(size_t)z * NPIX + colBase + tid], sred[tid]);
            atomicAdd(&g_sum2Y[(size_t)z * NPIX + colBase + tid], sred2[tid]);
        }
    }
}

// ---------------- q softmax over channel dim (96) per (b,h,pixel), fp16 io ----------------
__global__ __launch_bounds__(128) void q_softmax_kernel()
{
    int idx = blockIdx.x * blockDim.x + threadIdx.x;
    if (idx >= BATCH * HEADS * NPIX) return;
    int pix = idx & 4095;
    int h   = (idx >> 12) & 3;
    int b   = idx >> 14;
    __half* base = g_qkvh + ((size_t)b * QKVROWS + h * CH) * NPIX + pix;

    float v[CH];
    float mx = -1e30f;
    #pragma unroll
    for (int d = 0; d < CH; d++) {
        v[d] = __half2float(base[(size_t)d * NPIX]);
        mx = fmaxf(mx, v[d]);
    }
    float s = 0.f;
    #pragma unroll
    for (int d = 0; d < CH; d++) {
        v[d] = __expf(v[d] - mx);
        s += v[d];
    }
    float inv = QSCALE / s;
    #pragma unroll
    for (int d = 0; d < CH; d++) base[(size_t)d * NPIX] = __float2half_rn(v[d] * inv);
}

// ---------------- k softmax over spatial dim (4096) per (b, channel), fp16 io ----------------
__global__ __launch_bounds__(256) void k_softmax_kernel()
{
    int row = blockIdx.x;
    int b = row / DIMC, r = row % DIMC;
    __half* base = g_qkvh + ((size_t)b * QKVROWS + DIMC + r) * NPIX;
    int tid  = threadIdx.x;
    int lane = tid & 31, warp = tid >> 5;

    float f[16];
    float mx = -1e30f;
    #pragma unroll
    for (int j = 0; j < 2; j++) {
        uint4 u = *(const uint4*)&base[(size_t)(j * 256 + tid) * 8];
        const __half2* hp = (const __half2*)&u;
        #pragma unroll
        for (int t = 0; t < 4; t++) {
            float2 p = __half22float2(hp[t]);
            f[j * 8 + 2 * t]     = p.x;
            f[j * 8 + 2 * t + 1] = p.y;
            mx = fmaxf(mx, fmaxf(p.x, p.y));
        }
    }
    __shared__ float smax[8];
    __shared__ float ssum[8];
    #pragma unroll
    for (int o = 16; o > 0; o >>= 1) mx = fmaxf(mx, __shfl_xor_sync(0xffffffffu, mx, o));
    if (lane == 0) smax[warp] = mx;
    __syncthreads();
    mx = smax[0];
    #pragma unroll
    for (int w = 1; w < 8; w++) mx = fmaxf(mx, smax[w]);

    float s = 0.f;
    #pragma unroll
    for (int t = 0; t < 16; t++) {
        f[t] = __expf(f[t] - mx);
        s += f[t];
    }
    #pragma unroll
    for (int o = 16; o > 0; o >>= 1) s += __shfl_xor_sync(0xffffffffu, s, o);
    if (lane == 0) ssum[warp] = s;
    __syncthreads();
    s = 0.f;
    #pragma unroll
    for (int w = 0; w < 8; w++) s += ssum[w];

    float inv = 1.f / s;
    #pragma unroll
    for (int j = 0; j < 2; j++) {
        uint4 u;
        __half2* hp = (__half2*)&u;
        #pragma unroll
        for (int t = 0; t < 4; t++)
            hp[t] = __floats2half2_rn(f[j * 8 + 2 * t] * inv, f[j * 8 + 2 * t + 1] * inv);
        *(uint4*)&base[(size_t)(j * 256 + tid) * 8] = u;
    }
}

// =======================================================================
// ctx via tf32 MMA: ctxT[e][d] = sum_n v[e,n]*k[d,n], fp16 inputs
// =======================================================================
#define BKC 16
__global__ __launch_bounds__(256)
void ctx_tf32_kernel()
{
    int sk = blockIdx.x;
    int bh = blockIdx.y;
    int b = bh >> 2, h = bh & 3;
    const __half* kb = g_qkvh + ((size_t)b * QKVROWS + DIMC     + h * CH) * NPIX;
    const __half* vb = g_qkvh + ((size_t)b * QKVROWS + 2 * DIMC + h * CH) * NPIX;

    __shared__ float As[BKC][CH + 4];
    __shared__ float Bs[BKC][CH + 4];

    int tid  = threadIdx.x;
    int lane = tid & 31;
    int wid  = tid >> 5;
    int warpM = wid & 1;
    int warpN = wid >> 1;
    int gid = lane >> 2;
    int tig = lane & 3;

    float acc[3][3][4];
    #pragma unroll
    for (int i = 0; i < 3; i++)
        #pragma unroll
        for (int j = 0; j < 3; j++)
            #pragma unroll
            for (int t = 0; t < 4; t++) acc[i][j][t] = 0.f;

    const int KLEN = NPIX / CTX_SPLIT;
    int n0 = sk * KLEN;

    for (int nt = 0; nt < KLEN; nt += BKC) {
        #pragma unroll
        for (int i = 0; i < 2; i++) {
            int idx = tid + i * 256;
            if (idx < 384) {
                int r  = idx >> 2;
                int c4 = (idx & 3) << 2;
                const __half2* pv = (const __half2*)&vb[(size_t)r * NPIX + n0 + nt + c4];
                float2 v0 = __half22float2(pv[0]);
                float2 v1 = __half22float2(pv[1]);
                As[c4 + 0][r] = v0.x; As[c4 + 1][r] = v0.y;
                As[c4 + 2][r] = v1.x; As[c4 + 3][r] = v1.y;
                const __half2* pk = (const __half2*)&kb[(size_t)r * NPIX + n0 + nt + c4];
                float2 k0 = __half22float2(pk[0]);
                float2 k1 = __half22float2(pk[1]);
                Bs[c4 + 0][r] = k0.x; Bs[c4 + 1][r] = k0.y;
                Bs[c4 + 2][r] = k1.x; Bs[c4 + 3][r] = k1.y;
            }
        }
        __syncthreads();

        #pragma unroll
        for (int ks = 0; ks < 2; ks++) {
            int kb8 = ks * 8;
            unsigned af[3][4];
            #pragma unroll
            for (int i = 0; i < 3; i++) {
                int mr = warpM * 48 + i * 16 + gid;
                af[i][0] = __float_as_uint(As[kb8 + tig    ][mr]);
                af[i][1] = __float_as_uint(As[kb8 + tig    ][mr + 8]);
                af[i][2] = __float_as_uint(As[kb8 + tig + 4][mr]);
                af[i][3] = __float_as_uint(As[kb8 + tig + 4][mr + 8]);
            }
            unsigned bf[3][2];
            #pragma unroll
            for (int j = 0; j < 3; j++) {
                int nc = warpN * 24 + j * 8 + gid;
                bf[j][0] = __float_as_uint(Bs[kb8 + tig    ][nc]);
                bf[j][1] = __float_as_uint(Bs[kb8 + tig + 4][nc]);
            }
            #pragma unroll
            for (int i = 0; i < 3; i++)
                #pragma unroll
                for (int j = 0; j < 3; j++) {
                    asm volatile(
                        "mma.sync.aligned.m16n8k8.row.col.f32.tf32.tf32.f32 "
                        "{%0,%1,%2,%3},{%4,%5,%6,%7},{%8,%9},{%0,%1,%2,%3};\n"
                        : "+f"(acc[i][j][0]), "+f"(acc[i][j][1]),
                          "+f"(acc[i][j][2]), "+f"(acc[i][j][3])
                        : "r"(af[i][0]), "r"(af[i][1]), "r"(af[i][2]), "r"(af[i][3]),
                          "r"(bf[j][0]), "r"(bf[j][1]));
                }
        }
        __syncthreads();
    }

    float* cb = g_ctxT + (size_t)bh * CH * CH;
    #pragma unroll
    for (int i = 0; i < 3; i++) {
        int e0 = warpM * 48 + i * 16 + gid;
        int e1 = e0 + 8;
        #pragma unroll
        for (int j = 0; j < 3; j++) {
            int d0 = warpN * 24 + j * 8 + 2 * tig;
            atomicAdd(&cb[e0 * CH + d0    ], acc[i][j][0]);
            atomicAdd(&cb[e0 * CH + d0 + 1], acc[i][j][1]);
            atomicAdd(&cb[e1 * CH + d0    ], acc[i][j][2]);
            atomicAdd(&cb[e1 * CH + d0 + 1], acc[i][j][3]);
        }
    }
}

// =======================================================================
// fold: Wfold_b[o, h*96+d] = sum_e Wout[o, h*96+e] * ctxT_bh[e, d]
// grid (6, 64): x = 64-row o-tile, y = bh. 256 thr: o = tid>>2, d-quarter = tid&3.
// =======================================================================
__global__ __launch_bounds__(256) void fold_w_kernel(const float* __restrict__ Wout)
{
    int bh = blockIdx.y;
    int b = bh >> 2, h = bh & 3;
    int oBase = blockIdx.x * 64;
    int tid = threadIdx.x;

    __shared__ float cs[CH * (CH + 1)];   // ctxT_bh padded [e][d], 37.2 KB

    const float* ct = g_ctxT + (size_t)bh * CH * CH;
    for (int i = tid; i < CH * CH; i += 256) {
        int e = i / CH, d = i - e * CH;
        cs[e * (CH + 1) + d] = ct[i];
    }
    __syncthreads();

    int o     = oBase + (tid >> 2);
    int dBase = (tid & 3) * 24;
    const float* wrow = Wout + (size_t)o * DIMC + h * CH;

    float acc[24];
    #pragma unroll
    for (int d = 0; d < 24; d++) acc[d] = 0.f;

    #pragma unroll 4
    for (int e = 0; e < CH; e++) {
        float w = wrow[e];                       // broadcast within quad
        const float* crow = &cs[e * (CH + 1) + dBase];
        #pragma unroll
        for (int d = 0; d < 24; d++) acc[d] += w * crow[d];
    }

    float* dst = g_Wfold + ((size_t)b * DIMC + o) * DIMC + h * CH + dBase;
    #pragma unroll
    for (int d = 0; d < 24; d++) dst[d] = acc[d];
}

// ---------------- final: LN(y from sums)*outg + (x-mean)*rstd*preg ----------------
__global__ void final_kernel(const float* __restrict__ x, const float* __restrict__ preg,
                             const float* __restrict__ outg, float* __restrict__ out)
{
    size_t i = (size_t)blockIdx.x * blockDim.x + threadIdx.x;
    if (i >= (size_t)BATCH * DIMC * NPIX) return;
    int pix = (int)(i & 4095);
    int bc  = (int)(i >> 12);
    int c   = bc % DIMC;
    int b   = bc / DIMC;
    int bp  = b * NPIX + pix;
    float m2  = g_sumY[bp] * (1.f / DIMC);
    float var = g_sum2Y[bp] * (1.f / DIMC) - m2 * m2;
    float r2  = rsqrtf(var + 1e-5f);
    float xn = (x[i] - g_mean[bp]) * g_rstd[bp] * preg[c];
    float yn = (__half2float(g_yh[i]) - m2) * r2 * outg[c];
    out[i] = yn + xn;
}

// ---------------- launch ----------------
extern "C" void kernel_launch(void* const* d_in, const int* in_sizes, int n_in,
                              void* d_out, int out_size)
{
    const float* x    = (const float*)d_in[0];
    const float* preg = (const float*)d_in[1];
    const float* Wqkv = (const float*)d_in[2];
    const float* Wout = (const float*)d_in[3];
    const float* bout = (const float*)d_in[4];
    const float* outg = (const float*)d_in[5];
    float* out = (float*)d_out;
    (void)in_sizes; (void)n_in; (void)out_size;

    // 1. prep folded weights + zero accumulators
    prep_w_kernel<<<(QKVROWS * 32 + 255) / 256, 256>>>(Wqkv, preg);
    zero_kernel<<<(BATCH * HEADS * CH * CH + 255) / 256, 256>>>();

    // 2. QKV GEMM with fused prenorm stats + LN epilogue
    h16gemm_kernel<0, QKVROWS, DIMC><<<dim3(NPIX / BN, QKVROWS / BM, BATCH), 256>>>(x, nullptr);

    // 3. softmaxes (in place, fp16)
    q_softmax_kernel<<<(BATCH * HEADS * NPIX) / 128, 128>>>();
    k_softmax_kernel<<<BATCH * DIMC, 256>>>();

    // 4. context, then fold ctxT into Wout (deletes the apply GEMM)
    ctx_tf32_kernel<<<dim3(CTX_SPLIT, BATCH * HEADS), 256>>>();
    fold_w_kernel<<<dim3(DIMC / 64, BATCH * HEADS), 256>>>(Wout);

    // 5. fused apply+projection GEMM: y = Wfold_b @ q (+bias), fp16 out, fused LN sums
    h16gemm_kernel<1, DIMC, DIMC><<<dim3(NPIX / BN, DIMC / BM, BATCH), 256>>>(nullptr, bout);

    // 6. fused LN/residual epilogue (stats from sums)
    final_kernel<<<(int)(((size_t)BATCH * DIMC * NPIX + 255) / 256), 256>>>(x, preg, outg, out);
}

// round 14
// speedup vs baseline: 1.2008x; 1.0492x over previous
#include <cuda_runtime.h>
#include <cuda_fp16.h>
#include <math.h>

// ---------------- problem constants ----------------
#define DIMC   384
#define NPIX   4096
#define BATCH  16
#define HEADS  4
#define CH     96
#define QKVROWS 1152
#define QSCALE 0.1020620726159658f   // 96^-0.5
#define CTX_SPLIT 8

// ---------------- scratch (device globals; allocation-free contract) ----------------
__device__ __half g_Wgh[QKVROWS * DIMC];                    // fp16 folded weights
__device__ float  g_wsum[QKVROWS];
__device__ float  g_mean[BATCH * NPIX];
__device__ float  g_rstd[BATCH * NPIX];
__device__ float  g_sumY[BATCH * NPIX];                     // out-LN sums (atomics)
__device__ float  g_sum2Y[BATCH * NPIX];
__device__ __half g_qkvh[(size_t)BATCH * QKVROWS * NPIX];   // 151 MB, fp16
__device__ float  g_ctxT[BATCH * HEADS * CH * CH];          // ctx^T: [bh][e][d]
__device__ __half g_Wfoldh[(size_t)BATCH * DIMC * DIMC];    // folded Wout@ctxT, fp16
__device__ __half g_yh[(size_t)BATCH * DIMC * NPIX];        // 50 MB, fp16

// ---------------- prep: zero accumulators + W' = fp16(Wqkv*g), row sums ----------------
__global__ void prep_w_kernel(const float* __restrict__ W, const float* __restrict__ g)
{
    int gtid = blockIdx.x * blockDim.x + threadIdx.x;
    int nthr = gridDim.x * blockDim.x;
    for (int i = gtid; i < BATCH * HEADS * CH * CH; i += nthr) g_ctxT[i] = 0.f;
    for (int i = gtid; i < BATCH * NPIX; i += nthr) { g_sumY[i] = 0.f; g_sum2Y[i] = 0.f; }

    int warp = gtid >> 5;
    int lane = threadIdx.x & 31;
    if (warp >= QKVROWS) return;
    float s = 0.f;
    for (int c = lane; c < DIMC; c += 32) {
        __half wh = __float2half_rn(W[warp * DIMC + c] * g[c]);
        g_Wgh[warp * DIMC + c] = wh;
        s += __half2float(wh);
    }
    #pragma unroll
    for (int o = 16; o > 0; o >>= 1) s += __shfl_down_sync(0xffffffffu, s, o);
    if (lane == 0) g_wsum[warp] = s;
}

// ---------------- ldmatrix helper ----------------
__device__ __forceinline__ void ldsm_x4(unsigned &r0, unsigned &r1, unsigned &r2, unsigned &r3,
                                        unsigned addr)
{
    asm volatile("ldmatrix.sync.aligned.m8n8.x4.shared.b16 {%0,%1,%2,%3}, [%4];"
                 : "=r"(r0), "=r"(r1), "=r"(r2), "=r"(r3) : "r"(addr));
}

// =======================================================================
// fp16 tensor-core GEMM (fp32 accum): 128x128x16, 256 thr (8 warps 4x2),
// warp tile 32x64, mma.sync.m16n8k16, double-buffered smem, LDSM frags,
// half A-operand (1 LDG.128 + 1 STS.128 per thread per tile).
// KIND 0: qkv(h) = rstd*(Wgh@x - mean*wsum)  + fused prenorm stats
// KIND 1: y(h)   = Wfoldh_b@q + bout         + fused out-LN partial sums
// =======================================================================
#define BM 128
#define BN 128
#define BK 16
#define PADH 8                       // k-stride = 24 halves = 48B (16B-aligned)
#define KSTR (BK + PADH)             // 24
#define STAGEB (128 * KSTR * 2)      // bytes per stage = 6144

template<int KIND, int M, int K>
__global__ __launch_bounds__(256, 2)
void h16gemm_kernel(const float* __restrict__ Bext, const float* __restrict__ bias)
{
    const int N = NPIX;
    constexpr bool HALF_B = (KIND != 0);
    __shared__ __half As[2][BM][KSTR];
    __shared__ __half Bs[2][BN][KSTR];
    __shared__ float  sred[256], sred2[256];
    __shared__ float  meanS[BN], rstdS[BN];

    int z = blockIdx.z;
    const __half* Ah;
    const float* Bf = nullptr; const __half* Bh = nullptr;
    __half* Ch;

    if (KIND == 0) {
        Ah = g_Wgh;
        Bf = Bext + (size_t)z * K * N;
        Ch = g_qkvh + (size_t)z * M * N;
    } else {
        Ah = g_Wfoldh + (size_t)z * DIMC * DIMC;
        Bh = g_qkvh + (size_t)z * QKVROWS * N;   // q region (rows 0..383)
        Ch = g_yh + (size_t)z * M * N;
    }

    int tid  = threadIdx.x;
    int lane = tid & 31;
    int wid  = tid >> 5;
    int warpM = wid & 3;
    int warpN = wid >> 2;
    int gid = lane >> 2;
    int tig = lane & 3;

    int rowBase = blockIdx.y * BM;
    int colBase = blockIdx.x * BN;

    // A-load coords: 2 threads per row, 8 halves (16B) each
    int ar   = tid >> 1;
    int aseg = (tid & 1) * 8;
    const __half* aPtr = Ah + (size_t)(rowBase + ar) * K + aseg;

    // B-load coords
    int tn  = tid & 127;            // float-B path
    int kg  = tid >> 7;             // 0..1 -> 8 k rows each
    int tn2 = (tid & 63) << 1;      // half-B path: 2 columns
    int kg4 = tid >> 6;             // 0..3 -> 4 k rows each

    // LDSM addresses
    unsigned aBase = (unsigned)__cvta_generic_to_shared(&As[0][0][0]);
    unsigned bBase = (unsigned)__cvta_generic_to_shared(&Bs[0][0][0]);
    unsigned aOff0 = ((unsigned)((warpM * 32 + (lane & 15)) * KSTR + (lane >> 4) * 8)) * 2;
    unsigned bRow  = (unsigned)(warpN * 64 + ((lane >> 4) * 8) + (lane & 7));
    unsigned bOffB = (bRow * KSTR + ((lane >> 3) & 1) * 8) * 2;

    float acc[2][8][4];
    #pragma unroll
    for (int i = 0; i < 2; i++)
        #pragma unroll
        for (int j = 0; j < 8; j++)
            #pragma unroll
            for (int t = 0; t < 4; t++) acc[i][j][t] = 0.f;

    uint4   aRegH;
    float   bReg[8];
    __half2 bRegH[4];
    float   statS = 0.f, statS2 = 0.f;

    const int NT = K / BK;

    // ---- stage + commit tile 0 ----
    aRegH = *(const uint4*)aPtr;
    if (HALF_B) {
        #pragma unroll
        for (int j = 0; j < 4; j++)
            bRegH[j] = *(const __half2*)&Bh[(size_t)(kg4 * 4 + j) * N + colBase + tn2];
    } else {
        #pragma unroll
        for (int j = 0; j < 8; j++)
            bReg[j] = Bf[(size_t)(kg * 8 + j) * N + colBase + tn];
    }
    *(uint4*)&As[0][ar][aseg] = aRegH;
    if (HALF_B) {
        #pragma unroll
        for (int j = 0; j < 4; j++) {
            Bs[0][tn2    ][kg4 * 4 + j] = __low2half(bRegH[j]);
            Bs[0][tn2 + 1][kg4 * 4 + j] = __high2half(bRegH[j]);
        }
    } else {
        #pragma unroll
        for (int j = 0; j < 4; j++)
            *(half2*)&Bs[0][tn][kg * 8 + 2 * j] = __floats2half2_rn(bReg[2 * j], bReg[2 * j + 1]);
        if (KIND == 0) {
            #pragma unroll
            for (int j = 0; j < 8; j++) { statS += bReg[j]; statS2 += bReg[j] * bReg[j]; }
        }
    }
    __syncthreads();

    // ---- mainloop: 1 sync/iter ----
    for (int kt = 0; kt < NT; kt++) {
        int cur = kt & 1;
        bool hasNext = (kt + 1 < NT);

        if (hasNext) {
            int k1 = (kt + 1) * BK;
            aRegH = *(const uint4*)(aPtr + k1);
            if (HALF_B) {
                #pragma unroll
                for (int j = 0; j < 4; j++)
                    bRegH[j] = *(const __half2*)&Bh[(size_t)(k1 + kg4 * 4 + j) * N + colBase + tn2];
            } else {
                #pragma unroll
                for (int j = 0; j < 8; j++)
                    bReg[j] = Bf[(size_t)(k1 + kg * 8 + j) * N + colBase + tn];
            }
        }

        unsigned stOff = cur ? (unsigned)STAGEB : 0u;
        unsigned af[2][4];
        #pragma unroll
        for (int i = 0; i < 2; i++)
            ldsm_x4(af[i][0], af[i][1], af[i][2], af[i][3],
                    aBase + stOff + aOff0 + (unsigned)(i * 16 * KSTR * 2));
        unsigned bf[8][2];
        #pragma unroll
        for (int jj = 0; jj < 4; jj++) {
            unsigned r0, r1, r2, r3;
            ldsm_x4(r0, r1, r2, r3,
                    bBase + stOff + bOffB + (unsigned)(jj * 16 * KSTR * 2));
            bf[2 * jj][0]     = r0; bf[2 * jj][1]     = r1;
            bf[2 * jj + 1][0] = r2; bf[2 * jj + 1][1] = r3;
        }

        #pragma unroll
        for (int i = 0; i < 2; i++)
            #pragma unroll
            for (int j = 0; j < 8; j++) {
                asm volatile(
                    "mma.sync.aligned.m16n8k16.row.col.f32.f16.f16.f32 "
                    "{%0,%1,%2,%3},{%4,%5,%6,%7},{%8,%9},{%0,%1,%2,%3};\n"
                    : "+f"(acc[i][j][0]), "+f"(acc[i][j][1]),
                      "+f"(acc[i][j][2]), "+f"(acc[i][j][3])
                    : "r"(af[i][0]), "r"(af[i][1]), "r"(af[i][2]), "r"(af[i][3]),
                      "r"(bf[j][0]), "r"(bf[j][1]));
            }

        if (hasNext) {
            int nxt = cur ^ 1;
            *(uint4*)&As[nxt][ar][aseg] = aRegH;
            if (HALF_B) {
                #pragma unroll
                for (int j = 0; j < 4; j++) {
                    Bs[nxt][tn2    ][kg4 * 4 + j] = __low2half(bRegH[j]);
                    Bs[nxt][tn2 + 1][kg4 * 4 + j] = __high2half(bRegH[j]);
                }
            } else {
                #pragma unroll
                for (int j = 0; j < 4; j++)
                    *(half2*)&Bs[nxt][tn][kg * 8 + 2 * j] =
                        __floats2half2_rn(bReg[2 * j], bReg[2 * j + 1]);
                if (KIND == 0) {
                    #pragma unroll
                    for (int j = 0; j < 8; j++) { statS += bReg[j]; statS2 += bReg[j] * bReg[j]; }
                }
            }
        }
        __syncthreads();
    }

    // ---- KIND 0: block-local prenorm LN stats ----
    if (KIND == 0) {
        sred[tid] = statS; sred2[tid] = statS2;
        __syncthreads();
        if (tid < 128) {
            float st  = sred[tid]  + sred[tid + 128];
            float s2t = sred2[tid] + sred2[tid + 128];
            float m   = st * (1.f / DIMC);
            float var = s2t * (1.f / DIMC) - m * m;
            float r   = rsqrtf(var + 1e-5f);
            meanS[tid] = m; rstdS[tid] = r;
            if (blockIdx.y == 0) {
                g_mean[(size_t)z * NPIX + colBase + tid] = m;
                g_rstd[(size_t)z * NPIX + colBase + tid] = r;
            }
        }
        __syncthreads();
    }
    if (KIND == 1) {
        sred[tid] = 0.f; sred2[tid] = 0.f;
        __syncthreads();
    }

    float colS[16], colS2[16];
    if (KIND == 1) {
        #pragma unroll
        for (int t = 0; t < 16; t++) { colS[t] = 0.f; colS2[t] = 0.f; }
    }

    // ---------------- epilogue ----------------
    #pragma unroll
    for (int i = 0; i < 2; i++) {
        int r0 = rowBase + warpM * 32 + i * 16 + gid;
        int r1 = r0 + 8;
        float w0 = 0.f, w1 = 0.f, bb0 = 0.f, bb1 = 0.f;
        if (KIND == 0)      { w0 = g_wsum[r0]; w1 = g_wsum[r1]; }
        else                { bb0 = bias[r0];  bb1 = bias[r1]; }
        #pragma unroll
        for (int j = 0; j < 8; j++) {
            int cc = warpN * 64 + j * 8 + 2 * tig;
            int c0 = colBase + cc;
            if (KIND == 0) {
                float m0 = meanS[cc], m1 = meanS[cc + 1];
                float v0 = rstdS[cc], v1 = rstdS[cc + 1];
                *(half2*)&Ch[(size_t)r0 * N + c0] =
                    __floats2half2_rn(v0 * (acc[i][j][0] - m0 * w0),
                                      v1 * (acc[i][j][1] - m1 * w0));
                *(half2*)&Ch[(size_t)r1 * N + c0] =
                    __floats2half2_rn(v0 * (acc[i][j][2] - m0 * w1),
                                      v1 * (acc[i][j][3] - m1 * w1));
            } else {
                half2 h0 = __floats2half2_rn(acc[i][j][0] + bb0, acc[i][j][1] + bb0);
                half2 h1 = __floats2half2_rn(acc[i][j][2] + bb1, acc[i][j][3] + bb1);
                *(half2*)&Ch[(size_t)r0 * N + c0] = h0;
                *(half2*)&Ch[(size_t)r1 * N + c0] = h1;
                float2 f0 = __half22float2(h0);
                float2 f1 = __half22float2(h1);
                colS [2 * j]     += f0.x + f1.x;
                colS [2 * j + 1] += f0.y + f1.y;
                colS2[2 * j]     += f0.x * f0.x + f1.x * f1.x;
                colS2[2 * j + 1] += f0.y * f0.y + f1.y * f1.y;
            }
        }
    }

    if (KIND == 1) {
        #pragma unroll
        for (int t = 0; t < 8; t++) {
            int cc = warpN * 64 + t * 8 + 2 * tig;
            atomicAdd(&sred[cc],      colS[2 * t]);
            atomicAdd(&sred[cc + 1],  colS[2 * t + 1]);
            atomicAdd(&sred2[cc],     colS2[2 * t]);
            atomicAdd(&sred2[cc + 1], colS2[2 * t + 1]);
        }
        __syncthreads();
        if (tid < 128) {
            atomicAdd(&g_sumY [(size_t)z * NPIX + colBase + tid], sred[tid]);
            atomicAdd(&g_sum2Y[(size_t)z * NPIX + colBase + tid], sred2[tid]);
        }
    }
}

// ---------------- q softmax over channel dim (96) per (b,h,pixel), fp16 io ----------------
__global__ __launch_bounds__(128) void q_softmax_kernel()
{
    int idx = blockIdx.x * blockDim.x + threadIdx.x;
    if (idx >= BATCH * HEADS * NPIX) return;
    int pix = idx & 4095;
    int h   = (idx >> 12) & 3;
    int b   = idx >> 14;
    __half* base = g_qkvh + ((size_t)b * QKVROWS + h * CH) * NPIX + pix;

    float v[CH];
    float mx = -1e30f;
    #pragma unroll
    for (int d = 0; d < CH; d++) {
        v[d] = __half2float(base[(size_t)d * NPIX]);
        mx = fmaxf(mx, v[d]);
    }
    float s = 0.f;
    #pragma unroll
    for (int d = 0; d < CH; d++) {
        v[d] = __expf(v[d] - mx);
        s += v[d];
    }
    float inv = QSCALE / s;
    #pragma unroll
    for (int d = 0; d < CH; d++) base[(size_t)d * NPIX] = __float2half_rn(v[d] * inv);
}

// ---------------- k softmax over spatial dim (4096) per (b, channel), fp16 io ----------------
__global__ __launch_bounds__(256) void k_softmax_kernel()
{
    int row = blockIdx.x;
    int b = row / DIMC, r = row % DIMC;
    __half* base = g_qkvh + ((size_t)b * QKVROWS + DIMC + r) * NPIX;
    int tid  = threadIdx.x;
    int lane = tid & 31, warp = tid >> 5;

    float f[16];
    float mx = -1e30f;
    #pragma unroll
    for (int j = 0; j < 2; j++) {
        uint4 u = *(const uint4*)&base[(size_t)(j * 256 + tid) * 8];
        const __half2* hp = (const __half2*)&u;
        #pragma unroll
        for (int t = 0; t < 4; t++) {
            float2 p = __half22float2(hp[t]);
            f[j * 8 + 2 * t]     = p.x;
            f[j * 8 + 2 * t + 1] = p.y;
            mx = fmaxf(mx, fmaxf(p.x, p.y));
        }
    }
    __shared__ float smax[8];
    __shared__ float ssum[8];
    #pragma unroll
    for (int o = 16; o > 0; o >>= 1) mx = fmaxf(mx, __shfl_xor_sync(0xffffffffu, mx, o));
    if (lane == 0) smax[warp] = mx;
    __syncthreads();
    mx = smax[0];
    #pragma unroll
    for (int w = 1; w < 8; w++) mx = fmaxf(mx, smax[w]);

    float s = 0.f;
    #pragma unroll
    for (int t = 0; t < 16; t++) {
        f[t] = __expf(f[t] - mx);
        s += f[t];
    }
    #pragma unroll
    for (int o = 16; o > 0; o >>= 1) s += __shfl_xor_sync(0xffffffffu, s, o);
    if (lane == 0) ssum[warp] = s;
    __syncthreads();
    s = 0.f;
    #pragma unroll
    for (int w = 0; w < 8; w++) s += ssum[w];

    float inv = 1.f / s;
    #pragma unroll
    for (int j = 0; j < 2; j++) {
        uint4 u;
        __half2* hp = (__half2*)&u;
        #pragma unroll
        for (int t = 0; t < 4; t++)
            hp[t] = __floats2half2_rn(f[j * 8 + 2 * t] * inv, f[j * 8 + 2 * t + 1] * inv);
        *(uint4*)&base[(size_t)(j * 256 + tid) * 8] = u;
    }
}

// =======================================================================
// ctx via fp16 MMA (m16n8k16): ctxT[e][d] = sum_n v[e,n]*k[d,n]
// warp grid 2x4 (M 48, N 24), half smem [row][k], ldmatrix A frags.
// =======================================================================
#define KSTR2 24

__global__ __launch_bounds__(256)
void ctx_h16_kernel()
{
    int sk = blockIdx.x;
    int bh = blockIdx.y;
    int b = bh >> 2, h = bh & 3;
    const __half* kb = g_qkvh + ((size_t)b * QKVROWS + DIMC     + h * CH) * NPIX;
    const __half* vb = g_qkvh + ((size_t)b * QKVROWS + 2 * DIMC + h * CH) * NPIX;

    __shared__ __half As[CH][KSTR2];   // v: [e][nn]  (M x K)
    __shared__ __half Bs[CH][KSTR2];   // k: [d][nn]  (N x K)

    int tid  = threadIdx.x;
    int lane = tid & 31;
    int wid  = tid >> 5;
    int warpM = wid & 1;               // 0..1 -> 48-row slices (e)
    int warpN = wid >> 1;              // 0..3 -> 24-col slices (d)
    int gid = lane >> 2;
    int tig = lane & 3;

    unsigned aBase = (unsigned)__cvta_generic_to_shared(&As[0][0]);
    unsigned aOff0 = ((unsigned)((warpM * 48 + (lane & 15)) * KSTR2 + (lane >> 4) * 8)) * 2;

    float acc[3][3][4];
    #pragma unroll
    for (int i = 0; i < 3; i++)
        #pragma unroll
        for (int j = 0; j < 3; j++)
            #pragma unroll
            for (int t = 0; t < 4; t++) acc[i][j][t] = 0.f;

    const int KLEN = NPIX / CTX_SPLIT;   // 512
    int n0 = sk * KLEN;

    for (int nt = 0; nt < KLEN; nt += 16) {
        // load 96x16 halves of v and k: 192 + 192 uint4 segments
        #pragma unroll
        for (int i = 0; i < 2; i++) {
            int idx = tid + i * 256;
            if (idx < 192) {
                int r  = idx >> 1;
                int sg = (idx & 1) * 8;
                *(uint4*)&As[r][sg] = *(const uint4*)&vb[(size_t)r * NPIX + n0 + nt + sg];
            } else if (idx < 384) {
                int r  = (idx - 192) >> 1;
                int sg = (idx & 1) * 8;
                *(uint4*)&Bs[r][sg] = *(const uint4*)&kb[(size_t)r * NPIX + n0 + nt + sg];
            }
        }
        __syncthreads();

        unsigned af[3][4];
        #pragma unroll
        for (int i = 0; i < 3; i++)
            ldsm_x4(af[i][0], af[i][1], af[i][2], af[i][3],
                    aBase + aOff0 + (unsigned)(i * 16 * KSTR2 * 2));
        unsigned bf[3][2];
        #pragma unroll
        for (int j = 0; j < 3; j++) {
            int nc = warpN * 24 + j * 8 + gid;
            bf[j][0] = *(const unsigned*)&Bs[nc][2 * tig];
            bf[j][1] = *(const unsigned*)&Bs[nc][2 * tig + 8];
        }
        #pragma unroll
        for (int i = 0; i < 3; i++)
            #pragma unroll
            for (int j = 0; j < 3; j++) {
                asm volatile(
                    "mma.sync.aligned.m16n8k16.row.col.f32.f16.f16.f32 "
                    "{%0,%1,%2,%3},{%4,%5,%6,%7},{%8,%9},{%0,%1,%2,%3};\n"
                    : "+f"(acc[i][j][0]), "+f"(acc[i][j][1]),
                      "+f"(acc[i][j][2]), "+f"(acc[i][j][3])
                    : "r"(af[i][0]), "r"(af[i][1]), "r"(af[i][2]), "r"(af[i][3]),
                      "r"(bf[j][0]), "r"(bf[j][1]));
            }
        __syncthreads();
    }

    float* cb = g_ctxT + (size_t)bh * CH * CH;
    #pragma unroll
    for (int i = 0; i < 3; i++) {
        int e0 = warpM * 48 + i * 16 + gid;
        int e1 = e0 + 8;
        #pragma unroll
        for (int j = 0; j < 3; j++) {
            int d0 = warpN * 24 + j * 8 + 2 * tig;
            atomicAdd(&cb[e0 * CH + d0    ], acc[i][j][0]);
            atomicAdd(&cb[e0 * CH + d0 + 1], acc[i][j][1]);
            atomicAdd(&cb[e1 * CH + d0    ], acc[i][j][2]);
            atomicAdd(&cb[e1 * CH + d0 + 1], acc[i][j][3]);
        }
    }
}

// =======================================================================
// fold: Wfoldh_b[o, h*96+d] = fp16( sum_e Wout[o, h*96+e] * ctxT_bh[e, d] )
// =======================================================================
__global__ __launch_bounds__(256) void fold_w_kernel(const float* __restrict__ Wout)
{
    int bh = blockIdx.y;
    int b = bh >> 2, h = bh & 3;
    int oBase = blockIdx.x * 64;
    int tid = threadIdx.x;

    __shared__ float cs[CH * (CH + 1)];

    const float* ct = g_ctxT + (size_t)bh * CH * CH;
    for (int i = tid; i < CH * CH; i += 256) {
        int e = i / CH, d = i - e * CH;
        cs[e * (CH + 1) + d] = ct[i];
    }
    __syncthreads();

    int o     = oBase + (tid >> 2);
    int dBase = (tid & 3) * 24;
    const float* wrow = Wout + (size_t)o * DIMC + h * CH;

    float acc[24];
    #pragma unroll
    for (int d = 0; d < 24; d++) acc[d] = 0.f;

    #pragma unroll 4
    for (int e = 0; e < CH; e++) {
        float w = wrow[e];
        const float* crow = &cs[e * (CH + 1) + dBase];
        #pragma unroll
        for (int d = 0; d < 24; d++) acc[d] += w * crow[d];
    }

    __half* dst = g_Wfoldh + ((size_t)b * DIMC + o) * DIMC + h * CH + dBase;
    #pragma unroll
    for (int d = 0; d < 24; d++) dst[d] = __float2half_rn(acc[d]);
}

// ---------------- final: LN(y from sums)*outg + (x-mean)*rstd*preg ----------------
__global__ void final_kernel(const float* __restrict__ x, const float* __restrict__ preg,
                             const float* __restrict__ outg, float* __restrict__ out)
{
    size_t i = (size_t)blockIdx.x * blockDim.x + threadIdx.x;
    if (i >= (size_t)BATCH * DIMC * NPIX) return;
    int pix = (int)(i & 4095);
    int bc  = (int)(i >> 12);
    int c   = bc % DIMC;
    int b   = bc / DIMC;
    int bp  = b * NPIX + pix;
    float m2  = g_sumY[bp] * (1.f / DIMC);
    float var = g_sum2Y[bp] * (1.f / DIMC) - m2 * m2;
    float r2  = rsqrtf(var + 1e-5f);
    float xn = (x[i] - g_mean[bp]) * g_rstd[bp] * preg[c];
    float yn = (__half2float(g_yh[i]) - m2) * r2 * outg[c];
    out[i] = yn + xn;
}

// ---------------- launch ----------------
extern "C" void kernel_launch(void* const* d_in, const int* in_sizes, int n_in,
                              void* d_out, int out_size)
{
    const float* x    = (const float*)d_in[0];
    const float* preg = (const float*)d_in[1];
    const float* Wqkv = (const float*)d_in[2];
    const float* Wout = (const float*)d_in[3];
    const float* bout = (const float*)d_in[4];
    const float* outg = (const float*)d_in[5];
    float* out = (float*)d_out;
    (void)in_sizes; (void)n_in; (void)out_size;

    // 1. prep folded fp16 weights + zero accumulators (merged)
    prep_w_kernel<<<(QKVROWS * 32 + 255) / 256, 256>>>(Wqkv, preg);

    // 2. QKV GEMM with fused prenorm stats + LN epilogue
    h16gemm_kernel<0, QKVROWS, DIMC><<<dim3(NPIX / BN, QKVROWS / BM, BATCH), 256>>>(x, nullptr);

    // 3. softmaxes (in place, fp16)
    q_softmax_kernel<<<(BATCH * HEADS * NPIX) / 128, 128>>>();
    k_softmax_kernel<<<BATCH * DIMC, 256>>>();

    // 4. context (fp16 MMA), then fold ctxT into Wout (fp16 out)
    ctx_h16_kernel<<<dim3(CTX_SPLIT, BATCH * HEADS), 256>>>();
    fold_w_kernel<<<dim3(DIMC / 64, BATCH * HEADS), 256>>>(Wout);

    // 5. fused apply+projection GEMM: y = Wfoldh_b @ q (+bias), fp16 out, fused LN sums
    h16gemm_kernel<1, DIMC, DIMC><<<dim3(NPIX / BN, DIMC / BM, BATCH), 256>>>(nullptr, bout);

    // 6. fused LN/residual epilogue (stats from sums)
    final_kernel<<<(int)(((size_t)BATCH * DIMC * NPIX + 255) / 256), 256>>>(x, preg, outg, out);
}

// round 17
// speedup vs baseline: 1.3269x; 1.1050x over previous
#include <cuda_runtime.h>
#include <cuda_fp16.h>
#include <math.h>

// ---------------- problem constants ----------------
#define DIMC   384
#define NPIX   4096
#define BATCH  16
#define HEADS  4
#define CH     96
#define QKVROWS 1152
#define QSCALE 0.1020620726159658f   // 96^-0.5
#define CTX_SPLIT 8

// ---------------- scratch (device globals; allocation-free contract) ----------------
__device__ __half g_Wgh[QKVROWS * DIMC];                    // fp16 folded weights
__device__ float  g_wsum[QKVROWS];
__device__ float  g_mean[BATCH * NPIX];
__device__ float  g_rstd[BATCH * NPIX];
__device__ float  g_sumY[BATCH * NPIX];                     // out-LN sums (atomics)
__device__ float  g_sum2Y[BATCH * NPIX];
__device__ __half g_qkvh[(size_t)BATCH * QKVROWS * NPIX];   // 151 MB, fp16
__device__ float  g_ctxT[BATCH * HEADS * CH * CH];          // ctx^T: [bh][e][d]
__device__ __half g_Wfoldh[(size_t)BATCH * DIMC * DIMC];    // folded Wout@ctxT, fp16
__device__ __half g_yh[(size_t)BATCH * DIMC * NPIX];        // 50 MB, fp16

// ---------------- prep: zero accumulators + W' = fp16(Wqkv*g), row sums ----------------
__global__ void prep_w_kernel(const float* __restrict__ W, const float* __restrict__ g)
{
    int gtid = blockIdx.x * blockDim.x + threadIdx.x;
    int nthr = gridDim.x * blockDim.x;
    for (int i = gtid; i < BATCH * HEADS * CH * CH; i += nthr) g_ctxT[i] = 0.f;
    for (int i = gtid; i < BATCH * NPIX; i += nthr) { g_sumY[i] = 0.f; g_sum2Y[i] = 0.f; }

    int warp = gtid >> 5;
    int lane = threadIdx.x & 31;
    if (warp >= QKVROWS) return;
    float s = 0.f;
    for (int c = lane; c < DIMC; c += 32) {
        __half wh = __float2half_rn(W[warp * DIMC + c] * g[c]);
        g_Wgh[warp * DIMC + c] = wh;
        s += __half2float(wh);
    }
    #pragma unroll
    for (int o = 16; o > 0; o >>= 1) s += __shfl_down_sync(0xffffffffu, s, o);
    if (lane == 0) g_wsum[warp] = s;
}

// ---------------- ldmatrix helper ----------------
__device__ __forceinline__ void ldsm_x4(unsigned &r0, unsigned &r1, unsigned &r2, unsigned &r3,
                                        unsigned addr)
{
    asm volatile("ldmatrix.sync.aligned.m8n8.x4.shared.b16 {%0,%1,%2,%3}, [%4];"
                 : "=r"(r0), "=r"(r1), "=r"(r2), "=r"(r3) : "r"(addr));
}

// =======================================================================
// fp16 tensor-core GEMM (fp32 accum): 128x128x32, 256 thr (8 warps 4x2),
// warp tile 32x64, mma.sync.m16n8k16, double-buffered smem (1 sync/iter,
// 12 iters for K=384), LDSM frags, half A-operand.
// KIND 0: qkv(h) = rstd*(Wgh@x - mean*wsum)  + fused prenorm stats
// KIND 1: y(h)   = Wfoldh_b@q + bout         + fused out-LN partial sums
// =======================================================================
#define BM 128
#define BN 128
#define BK 32
#define KSTR 40                      // k-stride in halves = 80B (16B-aligned rows)
#define STAGEB (128 * KSTR * 2)      // bytes per stage = 10240

template<int KIND, int M, int K>
__global__ __launch_bounds__(256, 2)
void h16gemm_kernel(const float* __restrict__ Bext, const float* __restrict__ bias)
{
    const int N = NPIX;
    constexpr bool HALF_B = (KIND != 0);
    __shared__ __half As[2][BM][KSTR];
    __shared__ __half Bs[2][BN][KSTR];
    __shared__ float  sred[256], sred2[256];
    __shared__ float  meanS[BN], rstdS[BN];

    int z = blockIdx.z;
    const __half* Ah;
    const float* Bf = nullptr; const __half* Bh = nullptr;
    __half* Ch;

    if (KIND == 0) {
        Ah = g_Wgh;
        Bf = Bext + (size_t)z * K * N;
        Ch = g_qkvh + (size_t)z * M * N;
    } else {
        Ah = g_Wfoldh + (size_t)z * DIMC * DIMC;
        Bh = g_qkvh + (size_t)z * QKVROWS * N;   // q region (rows 0..383)
        Ch = g_yh + (size_t)z * M * N;
    }

    int tid  = threadIdx.x;
    int lane = tid & 31;
    int wid  = tid >> 5;
    int warpM = wid & 3;
    int warpN = wid >> 2;
    int gid = lane >> 2;
    int tig = lane & 3;

    int rowBase = blockIdx.y * BM;
    int colBase = blockIdx.x * BN;

    // A-load: 2 threads per row, 16 halves (2x uint4) each
    int ar   = tid >> 1;
    int aseg = (tid & 1) * 16;
    const __half* aPtr = Ah + (size_t)(rowBase + ar) * K + aseg;

    // B-load coords
    int tn  = tid & 127;            // float-B: one column, 16 k-rows
    int kg  = tid >> 7;             // 0..1 -> 16 k rows each
    int tn2 = (tid & 63) << 1;      // half-B: 2 columns, 8 k-rows
    int kg4 = tid >> 6;             // 0..3 -> 8 k rows each

    // LDSM addresses
    unsigned aBase = (unsigned)__cvta_generic_to_shared(&As[0][0][0]);
    unsigned bBase = (unsigned)__cvta_generic_to_shared(&Bs[0][0][0]);
    unsigned aOff0 = ((unsigned)((warpM * 32 + (lane & 15)) * KSTR + (lane >> 4) * 8)) * 2;
    unsigned bRow  = (unsigned)(warpN * 64 + ((lane >> 4) * 8) + (lane & 7));
    unsigned bOffB = (bRow * KSTR + ((lane >> 3) & 1) * 8) * 2;

    float acc[2][8][4];
    #pragma unroll
    for (int i = 0; i < 2; i++)
        #pragma unroll
        for (int j = 0; j < 8; j++)
            #pragma unroll
            for (int t = 0; t < 4; t++) acc[i][j][t] = 0.f;

    uint4   aRegH[2];
    float   bReg[16];
    __half2 bRegH[8];
    float   statS = 0.f, statS2 = 0.f;

    const int NT = K / BK;   // 12

    // ---- stage + commit tile 0 ----
    aRegH[0] = *(const uint4*)aPtr;
    aRegH[1] = *(const uint4*)(aPtr + 8);
    if (HALF_B) {
        #pragma unroll
        for (int j = 0; j < 8; j++)
            bRegH[j] = *(const __half2*)&Bh[(size_t)(kg4 * 8 + j) * N + colBase + tn2];
    } else {
        #pragma unroll
        for (int j = 0; j < 16; j++)
            bReg[j] = Bf[(size_t)(kg * 16 + j) * N + colBase + tn];
    }
    *(uint4*)&As[0][ar][aseg]     = aRegH[0];
    *(uint4*)&As[0][ar][aseg + 8] = aRegH[1];
    if (HALF_B) {
        #pragma unroll
        for (int j = 0; j < 8; j += 2) {
            *(half2*)&Bs[0][tn2    ][kg4 * 8 + j] = __lows2half2 (bRegH[j], bRegH[j + 1]);
            *(half2*)&Bs[0][tn2 + 1][kg4 * 8 + j] = __highs2half2(bRegH[j], bRegH[j + 1]);
        }
    } else {
        #pragma unroll
        for (int j = 0; j < 8; j++)
            *(half2*)&Bs[0][tn][kg * 16 + 2 * j] = __floats2half2_rn(bReg[2 * j], bReg[2 * j + 1]);
        if (KIND == 0) {
            #pragma unroll
            for (int j = 0; j < 16; j++) { statS += bReg[j]; statS2 += bReg[j] * bReg[j]; }
        }
    }
    __syncthreads();

    // ---- mainloop: 1 sync/iter, 32 MMAs/iter ----
    for (int kt = 0; kt < NT; kt++) {
        int cur = kt & 1;
        bool hasNext = (kt + 1 < NT);

        if (hasNext) {
            int k1 = (kt + 1) * BK;
            aRegH[0] = *(const uint4*)(aPtr + k1);
            aRegH[1] = *(const uint4*)(aPtr + k1 + 8);
            if (HALF_B) {
                #pragma unroll
                for (int j = 0; j < 8; j++)
                    bRegH[j] = *(const __half2*)&Bh[(size_t)(k1 + kg4 * 8 + j) * N + colBase + tn2];
            } else {
                #pragma unroll
                for (int j = 0; j < 16; j++)
                    bReg[j] = Bf[(size_t)(k1 + kg * 16 + j) * N + colBase + tn];
            }
        }

        unsigned stOff = cur ? (unsigned)STAGEB : 0u;
        #pragma unroll
        for (int ks = 0; ks < 2; ks++) {
            unsigned kOff = stOff + (unsigned)(ks * 32);   // 16 halves = 32B
            unsigned af[2][4];
            #pragma unroll
            for (int i = 0; i < 2; i++)
                ldsm_x4(af[i][0], af[i][1], af[i][2], af[i][3],
                        aBase + kOff + aOff0 + (unsigned)(i * 16 * KSTR * 2));
            unsigned bf[8][2];
            #pragma unroll
            for (int jj = 0; jj < 4; jj++) {
                unsigned r0, r1, r2, r3;
                ldsm_x4(r0, r1, r2, r3,
                        bBase + kOff + bOffB + (unsigned)(jj * 16 * KSTR * 2));
                bf[2 * jj][0]     = r0; bf[2 * jj][1]     = r1;
                bf[2 * jj + 1][0] = r2; bf[2 * jj + 1][1] = r3;
            }
            #pragma unroll
            for (int i = 0; i < 2; i++)
                #pragma unroll
                for (int j = 0; j < 8; j++) {
                    asm volatile(
                        "mma.sync.aligned.m16n8k16.row.col.f32.f16.f16.f32 "
                        "{%0,%1,%2,%3},{%4,%5,%6,%7},{%8,%9},{%0,%1,%2,%3};\n"
                        : "+f"(acc[i][j][0]), "+f"(acc[i][j][1]),
                          "+f"(acc[i][j][2]), "+f"(acc[i][j][3])
                        : "r"(af[i][0]), "r"(af[i][1]), "r"(af[i][2]), "r"(af[i][3]),
                          "r"(bf[j][0]), "r"(bf[j][1]));
                }
        }

        if (hasNext) {
            int nxt = cur ^ 1;
            *(uint4*)&As[nxt][ar][aseg]     = aRegH[0];
            *(uint4*)&As[nxt][ar][aseg + 8] = aRegH[1];
            if (HALF_B) {
                #pragma unroll
                for (int j = 0; j < 8; j += 2) {
                    *(half2*)&Bs[nxt][tn2    ][kg4 * 8 + j] = __lows2half2 (bRegH[j], bRegH[j + 1]);
                    *(half2*)&Bs[nxt][tn2 + 1][kg4 * 8 + j] = __highs2half2(bRegH[j], bRegH[j + 1]);
                }
            } else {
                #pragma unroll
                for (int j = 0; j < 8; j++)
                    *(half2*)&Bs[nxt][tn][kg * 16 + 2 * j] =
                        __floats2half2_rn(bReg[2 * j], bReg[2 * j + 1]);
                if (KIND == 0) {
                    #pragma unroll
                    for (int j = 0; j < 16; j++) { statS += bReg[j]; statS2 += bReg[j] * bReg[j]; }
                }
            }
        }
        __syncthreads();
    }

    // ---- KIND 0: block-local prenorm LN stats (2 kg-groups per column) ----
    if (KIND == 0) {
        sred[tid] = statS; sred2[tid] = statS2;
        __syncthreads();
        if (tid < 128) {
            float st  = sred[tid]  + sred[tid + 128];
            float s2t = sred2[tid] + sred2[tid + 128];
            float m   = st * (1.f / DIMC);
            float var = s2t * (1.f / DIMC) - m * m;
            float r   = rsqrtf(var + 1e-5f);
            meanS[tid] = m; rstdS[tid] = r;
            if (blockIdx.y == 0) {
                g_mean[(size_t)z * NPIX + colBase + tid] = m;
                g_rstd[(size_t)z * NPIX + colBase + tid] = r;
            }
        }
        __syncthreads();
    }
    if (KIND == 1) {
        sred[tid] = 0.f; sred2[tid] = 0.f;
        __syncthreads();
    }

    float colS[16], colS2[16];
    if (KIND == 1) {
        #pragma unroll
        for (int t = 0; t < 16; t++) { colS[t] = 0.f; colS2[t] = 0.f; }
    }

    // ---------------- epilogue ----------------
    #pragma unroll
    for (int i = 0; i < 2; i++) {
        int r0 = rowBase + warpM * 32 + i * 16 + gid;
        int r1 = r0 + 8;
        float w0 = 0.f, w1 = 0.f, bb0 = 0.f, bb1 = 0.f;
        if (KIND == 0)      { w0 = g_wsum[r0]; w1 = g_wsum[r1]; }
        else                { bb0 = bias[r0];  bb1 = bias[r1]; }
        #pragma unroll
        for (int j = 0; j < 8; j++) {
            int cc = warpN * 64 + j * 8 + 2 * tig;
            int c0 = colBase + cc;
            if (KIND == 0) {
                float m0 = meanS[cc], m1 = meanS[cc + 1];
                float v0 = rstdS[cc], v1 = rstdS[cc + 1];
                *(half2*)&Ch[(size_t)r0 * N + c0] =
                    __floats2half2_rn(v0 * (acc[i][j][0] - m0 * w0),
                                      v1 * (acc[i][j][1] - m1 * w0));
                *(half2*)&Ch[(size_t)r1 * N + c0] =
                    __floats2half2_rn(v0 * (acc[i][j][2] - m0 * w1),
                                      v1 * (acc[i][j][3] - m1 * w1));
            } else {
                half2 h0 = __floats2half2_rn(acc[i][j][0] + bb0, acc[i][j][1] + bb0);
                half2 h1 = __floats2half2_rn(acc[i][j][2] + bb1, acc[i][j][3] + bb1);
                *(half2*)&Ch[(size_t)r0 * N + c0] = h0;
                *(half2*)&Ch[(size_t)r1 * N + c0] = h1;
                float2 f0 = __half22float2(h0);
                float2 f1 = __half22float2(h1);
                colS [2 * j]     += f0.x + f1.x;
                colS [2 * j + 1] += f0.y + f1.y;
                colS2[2 * j]     += f0.x * f0.x + f1.x * f1.x;
                colS2[2 * j + 1] += f0.y * f0.y + f1.y * f1.y;
            }
        }
    }

    if (KIND == 1) {
        #pragma unroll
        for (int t = 0; t < 8; t++) {
            int cc = warpN * 64 + t * 8 + 2 * tig;
            atomicAdd(&sred[cc],      colS[2 * t]);
            atomicAdd(&sred[cc + 1],  colS[2 * t + 1]);
            atomicAdd(&sred2[cc],     colS2[2 * t]);
            atomicAdd(&sred2[cc + 1], colS2[2 * t + 1]);
        }
        __syncthreads();
        if (tid < 128) {
            atomicAdd(&g_sumY [(size_t)z * NPIX + colBase + tid], sred[tid]);
            atomicAdd(&g_sum2Y[(size_t)z * NPIX + colBase + tid], sred2[tid]);
        }
    }
}

// ---------------- q softmax over channel dim (96), 2 pixels/thread, fp16 io ----------------
__global__ __launch_bounds__(128) void q_softmax_kernel()
{
    int idx = blockIdx.x * blockDim.x + threadIdx.x;      // pixel-pair index
    if (idx >= BATCH * HEADS * NPIX / 2) return;
    int pix = (idx & 2047) * 2;
    int h   = (idx >> 11) & 3;
    int b   = idx >> 13;
    __half* base = g_qkvh + ((size_t)b * QKVROWS + h * CH) * NPIX + pix;

    __half2 v[CH];
    float mx0 = -1e30f, mx1 = -1e30f;
    #pragma unroll
    for (int d = 0; d < CH; d++) {
        v[d] = *(const __half2*)&base[(size_t)d * NPIX];
        float2 f = __half22float2(v[d]);
        mx0 = fmaxf(mx0, f.x); mx1 = fmaxf(mx1, f.y);
    }
    float s0 = 0.f, s1 = 0.f;
    #pragma unroll
    for (int d = 0; d < CH; d++) {
        float2 f = __half22float2(v[d]);
        float e0 = __expf(f.x - mx0);
        float e1 = __expf(f.y - mx1);
        s0 += e0; s1 += e1;
        v[d] = __floats2half2_rn(e0, e1);
    }
    __half2 inv = __floats2half2_rn(QSCALE / s0, QSCALE / s1);
    #pragma unroll
    for (int d = 0; d < CH; d++)
        *(__half2*)&base[(size_t)d * NPIX] = __hmul2(v[d], inv);
}

// ---------------- k softmax over spatial dim (4096) per (b, channel), fp16 io ----------------
__global__ __launch_bounds__(256) void k_softmax_kernel()
{
    int row = blockIdx.x;
    int b = row / DIMC, r = row % DIMC;
    __half* base = g_qkvh + ((size_t)b * QKVROWS + DIMC + r) * NPIX;
    int tid  = threadIdx.x;
    int lane = tid & 31, warp = tid >> 5;

    float f[16];
    float mx = -1e30f;
    #pragma unroll
    for (int j = 0; j < 2; j++) {
        uint4 u = *(const uint4*)&base[(size_t)(j * 256 + tid) * 8];
        const __half2* hp = (const __half2*)&u;
        #pragma unroll
        for (int t = 0; t < 4; t++) {
            float2 p = __half22float2(hp[t]);
            f[j * 8 + 2 * t]     = p.x;
            f[j * 8 + 2 * t + 1] = p.y;
            mx = fmaxf(mx, fmaxf(p.x, p.y));
        }
    }
    __shared__ float smax[8];
    __shared__ float ssum[8];
    #pragma unroll
    for (int o = 16; o > 0; o >>= 1) mx = fmaxf(mx, __shfl_xor_sync(0xffffffffu, mx, o));
    if (lane == 0) smax[warp] = mx;
    __syncthreads();
    mx = smax[0];
    #pragma unroll
    for (int w = 1; w < 8; w++) mx = fmaxf(mx, smax[w]);

    float s = 0.f;
    #pragma unroll
    for (int t = 0; t < 16; t++) {
        f[t] = __expf(f[t] - mx);
        s += f[t];
    }
    #pragma unroll
    for (int o = 16; o > 0; o >>= 1) s += __shfl_xor_sync(0xffffffffu, s, o);
    if (lane == 0) ssum[warp] = s;
    __syncthreads();
    s = 0.f;
    #pragma unroll
    for (int w = 0; w < 8; w++) s += ssum[w];

    float inv = 1.f / s;
    #pragma unroll
    for (int j = 0; j < 2; j++) {
        uint4 u;
        __half2* hp = (__half2*)&u;
        #pragma unroll
        for (int t = 0; t < 4; t++)
            hp[t] = __floats2half2_rn(f[j * 8 + 2 * t] * inv, f[j * 8 + 2 * t + 1] * inv);
        *(uint4*)&base[(size_t)(j * 256 + tid) * 8] = u;
    }
}

// =======================================================================
// ctx via fp16 MMA (m16n8k16): ctxT[e][d] = sum_n v[e,n]*k[d,n]
// =======================================================================
#define KSTR2 24

__global__ __launch_bounds__(256)
void ctx_h16_kernel()
{
    int sk = blockIdx.x;
    int bh = blockIdx.y;
    int b = bh >> 2, h = bh & 3;
    const __half* kb = g_qkvh + ((size_t)b * QKVROWS + DIMC     + h * CH) * NPIX;
    const __half* vb = g_qkvh + ((size_t)b * QKVROWS + 2 * DIMC + h * CH) * NPIX;

    __shared__ __half As[CH][KSTR2];   // v: [e][nn]
    __shared__ __half Bs[CH][KSTR2];   // k: [d][nn]

    int tid  = threadIdx.x;
    int lane = tid & 31;
    int wid  = tid >> 5;
    int warpM = wid & 1;
    int warpN = wid >> 1;
    int gid = lane >> 2;
    int tig = lane & 3;

    unsigned aBase = (unsigned)__cvta_generic_to_shared(&As[0][0]);
    unsigned aOff0 = ((unsigned)((warpM * 48 + (lane & 15)) * KSTR2 + (lane >> 4) * 8)) * 2;

    float acc[3][3][4];
    #pragma unroll
    for (int i = 0; i < 3; i++)
        #pragma unroll
        for (int j = 0; j < 3; j++)
            #pragma unroll
            for (int t = 0; t < 4; t++) acc[i][j][t] = 0.f;

    const int KLEN = NPIX / CTX_SPLIT;   // 512
    int n0 = sk * KLEN;

    for (int nt = 0; nt < KLEN; nt += 16) {
        #pragma unroll
        for (int i = 0; i < 2; i++) {
            int idx = tid + i * 256;
            if (idx < 192) {
                int r  = idx >> 1;
                int sg = (idx & 1) * 8;
                *(uint4*)&As[r][sg] = *(const uint4*)&vb[(size_t)r * NPIX + n0 + nt + sg];
            } else if (idx < 384) {
                int r  = (idx - 192) >> 1;
                int sg = (idx & 1) * 8;
                *(uint4*)&Bs[r][sg] = *(const uint4*)&kb[(size_t)r * NPIX + n0 + nt + sg];
            }
        }
        __syncthreads();

        unsigned af[3][4];
        #pragma unroll
        for (int i = 0; i < 3; i++)
            ldsm_x4(af[i][0], af[i][1], af[i][2], af[i][3],
                    aBase + aOff0 + (unsigned)(i * 16 * KSTR2 * 2));
        unsigned bf[3][2];
        #pragma unroll
        for (int j = 0; j < 3; j++) {
            int nc = warpN * 24 + j * 8 + gid;
            bf[j][0] = *(const unsigned*)&Bs[nc][2 * tig];
            bf[j][1] = *(const unsigned*)&Bs[nc][2 * tig + 8];
        }
        #pragma unroll
        for (int i = 0; i < 3; i++)
            #pragma unroll
            for (int j = 0; j < 3; j++) {
                asm volatile(
                    "mma.sync.aligned.m16n8k16.row.col.f32.f16.f16.f32 "
                    "{%0,%1,%2,%3},{%4,%5,%6,%7},{%8,%9},{%0,%1,%2,%3};\n"
                    : "+f"(acc[i][j][0]), "+f"(acc[i][j][1]),
                      "+f"(acc[i][j][2]), "+f"(acc[i][j][3])
                    : "r"(af[i][0]), "r"(af[i][1]), "r"(af[i][2]), "r"(af[i][3]),
                      "r"(bf[j][0]), "r"(bf[j][1]));
            }
        __syncthreads();
    }

    float* cb = g_ctxT + (size_t)bh * CH * CH;
    #pragma unroll
    for (int i = 0; i < 3; i++) {
        int e0 = warpM * 48 + i * 16 + gid;
        int e1 = e0 + 8;
        #pragma unroll
        for (int j = 0; j < 3; j++) {
            int d0 = warpN * 24 + j * 8 + 2 * tig;
            atomicAdd(&cb[e0 * CH + d0    ], acc[i][j][0]);
            atomicAdd(&cb[e0 * CH + d0 + 1], acc[i][j][1]);
            atomicAdd(&cb[e1 * CH + d0    ], acc[i][j][2]);
            atomicAdd(&cb[e1 * CH + d0 + 1], acc[i][j][3]);
        }
    }
}

// =======================================================================
// fold: Wfoldh_b[o, h*96+d] = fp16( sum_e Wout[o, h*96+e] * ctxT_bh[e, d] )
// =======================================================================
__global__ __launch_bounds__(256) void fold_w_kernel(const float* __restrict__ Wout)
{
    int bh = blockIdx.y;
    int b = bh >> 2, h = bh & 3;
    int oBase = blockIdx.x * 64;
    int tid = threadIdx.x;

    __shared__ float cs[CH * (CH + 1)];

    const float* ct = g_ctxT + (size_t)bh * CH * CH;
    for (int i = tid; i < CH * CH; i += 256) {
        int e = i / CH, d = i - e * CH;
        cs[e * (CH + 1) + d] = ct[i];
    }
    __syncthreads();

    int o     = oBase + (tid >> 2);
    int dBase = (tid & 3) * 24;
    const float* wrow = Wout + (size_t)o * DIMC + h * CH;

    float acc[24];
    #pragma unroll
    for (int d = 0; d < 24; d++) acc[d] = 0.f;

    #pragma unroll 4
    for (int e = 0; e < CH; e++) {
        float w = wrow[e];
        const float* crow = &cs[e * (CH + 1) + dBase];
        #pragma unroll
        for (int d = 0; d < 24; d++) acc[d] += w * crow[d];
    }

    __half* dst = g_Wfoldh + ((size_t)b * DIMC + o) * DIMC + h * CH + dBase;
    #pragma unroll
    for (int d = 0; d < 24; d++) dst[d] = __float2half_rn(acc[d]);
}

// ---------------- final: LN(y from sums)*outg + (x-mean)*rstd*preg ----------------
__global__ void final_kernel(const float* __restrict__ x, const float* __restrict__ preg,
                             const float* __restrict__ outg, float* __restrict__ out)
{
    size_t i = (size_t)blockIdx.x * blockDim.x + threadIdx.x;
    if (i >= (size_t)BATCH * DIMC * NPIX) return;
    int pix = (int)(i & 4095);
    int bc  = (int)(i >> 12);
    int c   = bc % DIMC;
    int b   = bc / DIMC;
    int bp  = b * NPIX + pix;
    float m2  = g_sumY[bp] * (1.f / DIMC);
    float var = g_sum2Y[bp] * (1.f / DIMC) - m2 * m2;
    float r2  = rsqrtf(var + 1e-5f);
    float xn = (x[i] - g_mean[bp]) * g_rstd[bp] * preg[c];
    float yn = (__half2float(g_yh[i]) - m2) * r2 * outg[c];
    out[i] = yn + xn;
}

// ---------------- launch ----------------
extern "C" void kernel_launch(void* const* d_in, const int* in_sizes, int n_in,
                              void* d_out, int out_size)
{
    const float* x    = (const float*)d_in[0];
    const float* preg = (const float*)d_in[1];
    const float* Wqkv = (const float*)d_in[2];
    const float* Wout = (const float*)d_in[3];
    const float* bout = (const float*)d_in[4];
    const float* outg = (const float*)d_in[5];
    float* out = (float*)d_out;
    (void)in_sizes; (void)n_in; (void)out_size;

    // 1. prep folded fp16 weights + zero accumulators (merged)
    prep_w_kernel<<<(QKVROWS * 32 + 255) / 256, 256>>>(Wqkv, preg);

    // 2. QKV GEMM (BK=32) with fused prenorm stats + LN epilogue
    h16gemm_kernel<0, QKVROWS, DIMC><<<dim3(NPIX / BN, QKVROWS / BM, BATCH), 256>>>(x, nullptr);

    // 3. softmaxes (in place, fp16)
    q_softmax_kernel<<<(BATCH * HEADS * NPIX / 2) / 128, 128>>>();
    k_softmax_kernel<<<BATCH * DIMC, 256>>>();

    // 4. context (fp16 MMA), then fold ctxT into Wout (fp16 out)
    ctx_h16_kernel<<<dim3(CTX_SPLIT, BATCH * HEADS), 256>>>();
    fold_w_kernel<<<dim3(DIMC / 64, BATCH * HEADS), 256>>>(Wout);

    // 5. fused apply+projection GEMM (BK=32): y = Wfoldh_b @ q (+bias), fused LN sums
    h16gemm_kernel<1, DIMC, DIMC><<<dim3(NPIX / BN, DIMC / BM, BATCH), 256>>>(nullptr, bout);

    // 6. fused LN/residual epilogue (stats from sums)
    final_kernel<<<(int)(((size_t)BATCH * DIMC * NPIX + 255) / 256), 256>>>(x, preg, outg, out);
}